// round 13
// baseline (speedup 1.0000x reference)
#include <cuda_runtime.h>
#include <cuda_bf16.h>
#include <math.h>
#include <cstdint>

#define BATCH 4096

#if defined(__CUDA_ARCH_FEAT_SM103_ALL) || defined(__CUDA_ARCH_FEAT_SM100_ALL)
#define HAS_TCGEN05 1
#else
#define HAS_TCGEN05 0
#endif

// ---------------- scratch (device globals; no allocation allowed) ----------------
__device__ int d_useTC;
__device__ int d_cntp[31 * 8];
__device__ float d_means[30 * BATCH * 64];
__device__ float d_feat[BATCH * 448];
__device__ float d_Wt[4 * 128 * 256];               // fp32 path
__device__ float d_bias[4 * 256];                   // fp32 path
__device__ __nv_bfloat16 d_Whi[4 * 2 * 16384];      // tc path
__device__ __nv_bfloat16 d_Wlo[4 * 2 * 16384];
__device__ float d_biasI[4 * 256];
__device__ __nv_bfloat16 d_xhi[20 * 32 * 8192];
__device__ __nv_bfloat16 d_xlo[20 * 32 * 8192];
__device__ float2 d_wideT[81 * 32];
__device__ float2 d_cqT[448 * 32];
__device__ float2 d_cquT[128 * 32];
__device__ float2 d_headB[4 * 32];

__constant__ int c_gstart[31] = {
    276,
    211, 224, 237, 250, 263,
    662, 672, 682, 692, 702,
    612, 622, 632, 642, 652,
    397, 410, 423, 436, 449,
    512, 522, 532, 542, 552,
    862, 872, 882, 892, 902};
__constant__ int c_grows[31] = {
    10,
    10, 10, 10, 10, 10,
    5, 5, 5, 5, 5,
    5, 5, 5, 5, 5,
    10, 10, 10, 10, 10,
    5, 5, 5, 5, 5,
    5, 5, 5, 5, 5};

__device__ __forceinline__ float sigf(float x) { return 1.0f / (1.0f + __expf(-x)); }
__device__ __forceinline__ float tanhfast(float x) {
    return fmaf(2.0f, 1.0f / (1.0f + __expf(-2.0f * x)), -1.0f);
}
__device__ __forceinline__ float tanha(float x) {
    float y;
    asm("tanh.approx.f32 %0, %1;" : "=f"(y) : "f"(x));
    return y;
}
__device__ __forceinline__ float siga(float x) {
    return fmaf(0.5f, tanha(0.5f * x), 0.5f);
}
__device__ __forceinline__ void cpa16(void* dst, const void* src) {
    unsigned a = (unsigned)__cvta_generic_to_shared(dst);
    asm volatile("cp.async.cg.shared.global [%0], [%1], 16;" ::"r"(a), "l"(src));
}
__device__ __forceinline__ uint32_t smem_u32(const void* p) {
    return (uint32_t)__cvta_generic_to_shared(p);
}
static __device__ __forceinline__ uint32_t swz128(uint32_t off) {
    return off ^ ((off >> 3) & 0x70);
}
typedef unsigned long long u64t;
__device__ __forceinline__ void fma2(u64t& d, u64t a, u64t b) {
    asm("fma.rn.f32x2 %0, %1, %2, %0;" : "+l"(d) : "l"(a), "l"(b));
}
__device__ __forceinline__ u64t pk2(float v) {
    u64t r;
    asm("mov.b64 %0, {%1, %1};" : "=l"(r) : "f"(v));
    return r;
}
__device__ __forceinline__ void up2(u64t v, float& lo, float& hi) {
    asm("mov.b64 {%0, %1}, %2;" : "=f"(lo), "=f"(hi) : "l"(v));
}
__device__ __forceinline__ uint32_t bf2pack(float a, float b) {
    __nv_bfloat162 h;
    h.x = __float2bfloat16(a);
    h.y = __float2bfloat16(b);
    return *(uint32_t*)&h;
}

// ---------------- prep + count fused ----------------
__global__ void prep_kernel(const float* __restrict__ Wih, const float* __restrict__ Whh,
                            const float* __restrict__ bih, const float* __restrict__ bhh,
                            const float* __restrict__ wide_w, const float* __restrict__ wide_b,
                            const float* __restrict__ cq_w, const float* __restrict__ cq_b,
                            const float* __restrict__ cqu_w, const float* __restrict__ cqu_b,
                            const float* __restrict__ dw_w, const float* __restrict__ x) {
    if (blockIdx.x >= 512) {
        int cb = blockIdx.x - 512;
        int g = cb >> 3;
        int part = cb & 7;
        int n = c_grows[g] * BATCH;
        const float* p = x + (size_t)c_gstart[g] * BATCH;
        int cnt = 0;
        for (int i = part * 256 + threadIdx.x; i < n; i += 2048) cnt += (p[i] != 0.0f);
#pragma unroll
        for (int o = 16; o; o >>= 1) cnt += __shfl_xor_sync(0xffffffffu, cnt, o);
        __shared__ int wsum[8];
        if ((threadIdx.x & 31) == 0) wsum[threadIdx.x >> 5] = cnt;
        __syncthreads();
        if (threadIdx.x == 0) {
            int s = 0;
#pragma unroll
            for (int w = 0; w < 8; w++) s += wsum[w];
            d_cntp[g * 8 + part] = s;
        }
        return;
    }
    int idx = blockIdx.x * 256 + threadIdx.x;  // 131072 total
    if (idx == 0) d_useTC = HAS_TCGEN05;
#if !HAS_TCGEN05
    {
        int c = idx & 255;
        int k = (idx >> 8) & 127;
        int i = idx >> 15;
        int h = ((c & 127) >> 2) + ((c >> 7) << 5);
        int t = c & 3;
        int g = t * 64 + h;
        float v = (k < 64) ? Wih[(i * 256 + g) * 64 + k]
                           : Whh[(i * 256 + g) * 64 + (k - 64)];
        d_Wt[idx] = v;
    }
    if (idx < 1024) {
        int i = idx >> 8;
        int c = idx & 255;
        int h = ((c & 127) >> 2) + ((c >> 7) << 5);
        int t = c & 3;
        int g = i * 256 + t * 64 + h;
        d_bias[idx] = bih[g] + bhh[g];
    }
#else
    {
        int i = idx >> 15;
        int rem = idx & 32767;
        int gb = rem >> 14;
        int rem2 = rem & 16383;
        int n = rem2 >> 7;
        int k = rem2 & 127;
        int t = n & 3;
        int hib = n >> 2;
        int g = t * 64 + 32 * gb + hib;
        float v = (k < 64) ? Wih[(i * 256 + g) * 64 + k]
                           : Whh[(i * 256 + g) * 64 + (k - 64)];
        __nv_bfloat16 hi = __float2bfloat16(v);
        __nv_bfloat16 lo = __float2bfloat16(v - __bfloat162float(hi));
        uint32_t off = ((uint32_t)(n >> 3) + ((uint32_t)(k >> 6) << 4)) * 1024u +
                       (uint32_t)(n & 7) * 128u + (uint32_t)(k & 63) * 2u;
        uint32_t sw = swz128(off) >> 1;
        int tile = i * 2 + gb;
        d_Whi[tile * 16384 + sw] = hi;
        d_Wlo[tile * 16384 + sw] = lo;
    }
    if (idx < 1024) {
        int i = idx >> 8;
        int c = idx & 255;
        int gb = c >> 7;
        int hib = (c & 127) >> 2;
        int t = c & 3;
        int src = i * 256 + t * 64 + 32 * gb + hib;
        d_biasI[idx] = bih[src] + bhh[src];
    }
#endif
    if (idx < 14336) {
        int j = idx >> 5, o = idx & 31;
        d_cqT[idx] = make_float2(cq_w[o * 448 + j], cq_w[(o + 32) * 448 + j]);
    }
    if (idx < 4096) {
        int j = idx >> 5, o = idx & 31;
        d_cquT[idx] = make_float2(cqu_w[o * 128 + j], cqu_w[(o + 32) * 128 + j]);
    }
    if (idx < 2592) {
        int j = idx >> 5, o = idx & 31;
        d_wideT[idx] = make_float2(wide_w[o * 81 + j], wide_w[(o + 32) * 81 + j]);
    }
    if (idx < 32) {
        d_headB[idx] = make_float2(wide_b[idx], wide_b[idx + 32]);
        d_headB[32 + idx] = make_float2(cq_b[idx], cq_b[idx + 32]);
        d_headB[64 + idx] = make_float2(cqu_b[idx], cqu_b[idx + 32]);
        d_headB[96 + idx] = make_float2(dw_w[idx], dw_w[idx + 32]);
    }
}

// ---------------- gathers + means ----------------
__global__ void mean_kernel(const float* __restrict__ x, const float* __restrict__ emb) {
    int w = blockIdx.x * 8 + (threadIdx.x >> 5);
    int lane = threadIdx.x & 31;
    int half = lane >> 4;
    int li = lane & 15;
    int g = w >> 11;
    int bp = w & 2047;
    int b = bp * 2 + half;

    int cpart = (lane < 8) ? d_cntp[g * 8 + lane] : 0;
#pragma unroll
    for (int o = 4; o; o >>= 1) cpart += __shfl_xor_sync(0xffffffffu, cpart, o);
    cpart = __shfl_sync(0xffffffffu, cpart, 0);
    float L = fminf(fmaxf((float)cpart, 1.0f), (float)c_grows[g]);
    int Lu = (int)(L + 0.5f);

    const float* xcol = x + (size_t)c_gstart[g] * BATCH + b;
    int tokr = 0;
    if (li < Lu) tokr = (int)xcol[(size_t)li * BATCH];

    float a0 = 0.0f, a1 = 0.0f, a2 = 0.0f, a3 = 0.0f;
    const float4* emb4 = (const float4*)emb;
#pragma unroll
    for (int r = 0; r < 10; r++) {
        if (r < Lu) {
            int tok = __shfl_sync(0xffffffffu, tokr, (lane & 16) + r);
            float4 v = __ldg(emb4 + (size_t)tok * 16 + li);
            a0 += v.x;
            a1 += v.y;
            a2 += v.z;
            a3 += v.w;
        }
    }
    float inv = 1.0f / L;
    a0 *= inv; a1 *= inv; a2 *= inv; a3 *= inv;

    if (g == 0) {
        ((float4*)(d_feat + (size_t)b * 448))[li] = make_float4(a0, a1, a2, a3);
    } else if (g <= 20 && d_useTC) {
        int row = b & 127;
        int tile = b >> 7;
        uint32_t off = (uint32_t)(row >> 3) * 1024u + (uint32_t)(row & 7) * 128u +
                       (uint32_t)li * 8u;
        uint32_t sw = swz128(off);
        uint32_t hi01 = bf2pack(a0, a1);
        uint32_t hi23 = bf2pack(a2, a3);
        __nv_bfloat16 h0 = __float2bfloat16(a0), h1 = __float2bfloat16(a1);
        __nv_bfloat16 h2 = __float2bfloat16(a2), h3 = __float2bfloat16(a3);
        uint32_t lo01 = bf2pack(a0 - __bfloat162float(h0), a1 - __bfloat162float(h1));
        uint32_t lo23 = bf2pack(a2 - __bfloat162float(h2), a3 - __bfloat162float(h3));
        size_t base = ((size_t)(g - 1) * 32 + tile) * 8192;
        *(u64t*)((char*)(d_xhi + base) + sw) = (u64t)hi01 | ((u64t)hi23 << 32);
        *(u64t*)((char*)(d_xlo + base) + sw) = (u64t)lo01 | ((u64t)lo23 << 32);
    } else {
        ((float4*)(d_means + ((size_t)(g - 1) * BATCH + b) * 64))[li] =
            make_float4(a0, a1, a2, a3);
    }
}

// ================= fused LSTM(tc) + CNN kernel =================
#define SM_AHI 0
#define SM_ALO 32768
#define SM_W 65536
#define SM_BIAS 196608
#define SM_PTR 197632
#define SM_MBAR0 197640
#define SM_MBAR1 197648
#define SM_HBUF 197664          // 128*65 floats
#define TC_SMEM_BYTES (197664 + 33280)

#if HAS_TCGEN05
static constexpr uint64_t SMEM_DESC_BASE_SW128 =
    (uint64_t(2) << 61) | (uint64_t(1) << 46) | (uint64_t(64) << 32) | (uint64_t(1) << 16);
#define MAKE_SMEM_DESC(base_addr) \
    (SMEM_DESC_BASE_SW128 | ((uint64_t)((base_addr) >> 4) & 0x3FFF))
#define LSTM_IDESC 0x8200490u

__device__ __forceinline__ uint32_t elect_one_pred() {
    uint32_t pred;
    asm volatile(
        "{\n\t.reg .pred p;\n\telect.sync _|p, 0xFFFFFFFF;\n\tselp.b32 %0, 1, 0, p;\n\t}"
        : "=r"(pred));
    return pred;
}
__device__ __forceinline__ void mma_f16_ss(uint32_t d, uint64_t a, uint64_t b,
                                           uint32_t idesc, bool accum) {
    uint32_t en = accum ? 1u : 0u;
    asm volatile(
        "{\n\t"
        ".reg .pred p;\n\t"
        "setp.ne.u32 p, %4, 0;\n\t"
        "tcgen05.mma.cta_group::1.kind::f16 [%0], %1, %2, %3, {%5, %5, %5, %5}, p;\n\t"
        "}"
        :: "r"(d), "l"(a), "l"(b), "r"(idesc), "r"(en), "r"(0u)
        : "memory");
}
#define TCGEN05_ALLOC(sa, n) \
    asm volatile("tcgen05.alloc.cta_group::1.sync.aligned.shared::cta.b32 [%0], %1;" ::"r"(sa), "r"(n) : "memory")
#define TCGEN05_DEALLOC(t, n) \
    asm volatile("tcgen05.dealloc.cta_group::1.sync.aligned.b32 %0, %1;" ::"r"(t), "r"(n))
#define TCGEN05_RELINQ() \
    asm volatile("tcgen05.relinquish_alloc_permit.cta_group::1.sync.aligned;")
#define TCGEN05_COMMIT(mb) \
    asm volatile("tcgen05.commit.cta_group::1.mbarrier::arrive::one.shared::cluster.b64 [%0];" ::"r"(mb) : "memory")
#define TCGEN05_FENCE_BEFORE() asm volatile("tcgen05.fence::before_thread_sync;" ::: "memory")
#define TCGEN05_FENCE_AFTER() asm volatile("tcgen05.fence::after_thread_sync;" ::: "memory")
#define TCGEN05_WAIT_LD() asm volatile("tcgen05.wait::ld.sync.aligned;" ::: "memory")
#define FENCE_PROXY_ASYNC() asm volatile("fence.proxy.async.shared::cta;" ::: "memory")
#define MBARRIER_INIT(mb, n) \
    asm volatile("mbarrier.init.shared.b64 [%0], %1;" ::"r"(mb), "r"(n) : "memory")
#define MBARRIER_WAIT_PARITY(mb, ph) do { \
    uint32_t _mb = (mb), _p = (ph), _done; \
    asm volatile("{\n\t.reg .pred p;\n\tmbarrier.try_wait.parity.acquire.cta.shared::cta.b64 p, [%1], %2;\n\tselp.b32 %0, 1, 0, p;\n\t}" \
        : "=r"(_done) : "r"(_mb), "r"(_p) : "memory"); \
    if (!_done) { \
        asm volatile("{\n\t.reg .pred P1;\n\tWL_%=:\n\tmbarrier.try_wait.parity.acquire.cta.shared::cta.b64 P1, [%0], %1, 0x989680;\n\t@P1 bra.uni WD_%=;\n\tbra.uni WL_%=;\n\tWD_%=:\n\t}" \
            :: "r"(_mb), "r"(_p) : "memory"); \
    } \
} while (0)
#define LDTM_X32(r, addr) \
    asm volatile( \
        "tcgen05.ld.sync.aligned.32x32b.x32.b32 " \
        "{%0, %1, %2, %3, %4, %5, %6, %7, %8, %9, %10, %11, %12, %13, %14, %15, " \
        " %16, %17, %18, %19, %20, %21, %22, %23, %24, %25, %26, %27, %28, %29, %30, %31}, [%32];" \
        : "=r"((r)[0]), "=r"((r)[1]), "=r"((r)[2]), "=r"((r)[3]), "=r"((r)[4]), "=r"((r)[5]), \
          "=r"((r)[6]), "=r"((r)[7]), "=r"((r)[8]), "=r"((r)[9]), "=r"((r)[10]), "=r"((r)[11]), \
          "=r"((r)[12]), "=r"((r)[13]), "=r"((r)[14]), "=r"((r)[15]), "=r"((r)[16]), "=r"((r)[17]), \
          "=r"((r)[18]), "=r"((r)[19]), "=r"((r)[20]), "=r"((r)[21]), "=r"((r)[22]), "=r"((r)[23]), \
          "=r"((r)[24]), "=r"((r)[25]), "=r"((r)[26]), "=r"((r)[27]), "=r"((r)[28]), "=r"((r)[29]), \
          "=r"((r)[30]), "=r"((r)[31]) \
        : "r"(addr))
#endif  // HAS_TCGEN05

// cnn work for one (s, b) item
__device__ __forceinline__ void cnn_item(const float* scw, const float* slw,
                                         const float* scb, const float* slb,
                                         int s, int b) {
    float y[12][4];
#pragma unroll
    for (int o = 0; o < 12; o++)
#pragma unroll
        for (int tt = 0; tt < 4; tt++) y[o][tt] = scb[s * 12 + o];

    const float* cwp = scw + s * 1536;
    int gbase = 20 + s * 5;
    for (int e4 = 0; e4 < 16; e4++) {
        float mv[5][4];
#pragma unroll
        for (int t = 0; t < 5; t++) {
            float4 m4 = *(const float4*)(d_means + ((size_t)(gbase + t) * BATCH + b) * 64 + e4 * 4);
            mv[t][0] = m4.x; mv[t][1] = m4.y; mv[t][2] = m4.z; mv[t][3] = m4.w;
        }
#pragma unroll
        for (int ee = 0; ee < 4; ee++) {
            int e = e4 * 4 + ee;
#pragma unroll
            for (int o = 0; o < 12; o++) {
                float w0 = cwp[o * 128 + e];
                float w1 = cwp[o * 128 + 64 + e];
#pragma unroll
                for (int tt = 0; tt < 4; tt++)
                    y[o][tt] = fmaf(mv[tt][ee], w0, fmaf(mv[tt + 1][ee], w1, y[o][tt]));
            }
        }
    }
    float p[24];
#pragma unroll
    for (int o = 0; o < 12; o++) {
#pragma unroll
        for (int j = 0; j < 2; j++)
            p[j * 12 + o] = fmaxf(fmaxf(y[o][2 * j], y[o][2 * j + 1]), 0.0f);
    }
    const float* lwp = slw + s * 1536;
    float* dst = d_feat + (size_t)b * 448 + 320 + s * 64;
    for (int eo = 0; eo < 64; eo++) {
        float acc = slb[s * 64 + eo];
#pragma unroll
        for (int j = 0; j < 24; j++) acc = fmaf(lwp[eo * 24 + j], p[j], acc);
        dst[eo] = fmaxf(acc, 0.0f);
    }
}

__global__ void __launch_bounds__(256, 1) lstm_tc_kernel(
    const float* __restrict__ h0, const float* __restrict__ c0,
    const float* __restrict__ w_l, const float* __restrict__ b_l,
    const float* __restrict__ cw1, const float* __restrict__ cb1,
    const float* __restrict__ lw1, const float* __restrict__ lb1,
    const float* __restrict__ cw2, const float* __restrict__ cb2,
    const float* __restrict__ lw2, const float* __restrict__ lb2) {
    extern __shared__ __align__(1024) char smem[];
    int tid = threadIdx.x;

    if (blockIdx.x >= 128) {
        // ---- CNN blocks (both arch paths) ----
        float* scw = (float*)smem;
        float* slw = scw + 3072;
        float* scb = slw + 3072;
        float* slb = scb + 32;
        for (int idx = tid; idx < 1536; idx += 256) {
            scw[idx] = cw1[idx];
            scw[1536 + idx] = cw2[idx];
            slw[idx] = lw1[idx];
            slw[1536 + idx] = lw2[idx];
        }
        if (tid < 12) {
            scb[tid] = cb1[tid];
            scb[12 + tid] = cb2[tid];
        }
        if (tid < 64) {
            slb[tid] = lb1[tid];
            slb[64 + tid] = lb2[tid];
        }
        __syncthreads();
        for (int item = (blockIdx.x - 128) * 256 + tid; item < 8192; item += 5120) {
            int s = item >> 12;
            int b = item & 4095;
            cnn_item(scw, slw, scb, slb, s, b);
        }
        return;
    }

#if HAS_TCGEN05
    uint32_t sbase = smem_u32(smem);
    int wid = tid >> 5;
    int lane = tid & 31;
    int i = blockIdx.x >> 5;
    int bx = blockIdx.x & 31;
    int b0 = bx * 128;

    if (wid == 0) {
        TCGEN05_ALLOC(sbase + SM_PTR, 256);
    } else {
        TCGEN05_RELINQ();
    }

    {
        const char* whi = (const char*)(d_Whi + (size_t)i * 2 * 16384);
        const char* wlo = (const char*)(d_Wlo + (size_t)i * 2 * 16384);
#pragma unroll
        for (int j = 0; j < 16; j++) {
            int ch = (tid + j * 256) * 16;
            cpa16(smem + SM_W + ch, whi + ch);
            cpa16(smem + SM_W + 65536 + ch, wlo + ch);
        }
        size_t xb = ((size_t)(i * 5) * 32 + bx) * 8192;
        const char* xh = (const char*)(d_xhi + xb);
        const char* xl = (const char*)(d_xlo + xb);
#pragma unroll
        for (int j = 0; j < 4; j++) {
            int ch = (tid + j * 256) * 16;
            cpa16(smem + SM_AHI + ch, xh + ch);
            cpa16(smem + SM_ALO + ch, xl + ch);
        }
    }
    asm volatile("cp.async.commit_group;");

    __syncthreads();
    uint32_t tmem;
    asm volatile("ld.shared.b32 %0, [%1];" : "=r"(tmem) : "r"(sbase + SM_PTR));

    for (int idx = tid; idx < 8192; idx += 256) {
        int row = idx >> 6, col = idx & 63;
        float v = h0[((size_t)(i << 12) + b0 + row) * 64 + col];
        __nv_bfloat16 hi = __float2bfloat16(v);
        __nv_bfloat16 lo = __float2bfloat16(v - __bfloat162float(hi));
        uint32_t off = ((uint32_t)(row >> 3) + 16u) * 1024u + (uint32_t)(row & 7) * 128u +
                       (uint32_t)col * 2u;
        uint32_t sw = swz128(off);
        *(__nv_bfloat16*)(smem + SM_AHI + sw) = hi;
        *(__nv_bfloat16*)(smem + SM_ALO + sw) = lo;
    }
    float* sBias = (float*)(smem + SM_BIAS);
    sBias[tid] = d_biasI[i * 256 + tid];

    int gb = wid >> 2;
    int bloc = ((wid & 3) << 5) + lane;
    uint32_t mymbar = sbase + (gb ? SM_MBAR1 : SM_MBAR0);

    float cR[32];
    {
        const float4* cp4 =
            (const float4*)(c0 + ((size_t)(i << 12) + b0 + bloc) * 64 + (gb << 5));
#pragma unroll
        for (int q = 0; q < 8; q++) {
            float4 v = cp4[q];
            cR[q * 4 + 0] = v.x;
            cR[q * 4 + 1] = v.y;
            cR[q * 4 + 2] = v.z;
            cR[q * 4 + 3] = v.w;
        }
    }

    if (tid == 0) {
        MBARRIER_INIT(sbase + SM_MBAR0, 1);
        MBARRIER_INIT(sbase + SM_MBAR1, 1);
    }
    __syncthreads();

    float* hbuf = (float*)(smem + SM_HBUF);

    for (int t = 0; t < 5; t++) {
        asm volatile("cp.async.wait_group 0;");
        __syncthreads();
        FENCE_PROXY_ASYNC();

        if (wid == 0) {
            TCGEN05_FENCE_AFTER();
            if (elect_one_pred()) {
                uint64_t ahi = MAKE_SMEM_DESC(sbase + SM_AHI);
                uint64_t alo = MAKE_SMEM_DESC(sbase + SM_ALO);
#pragma unroll
                for (int g2 = 0; g2 < 2; g2++) {
                    uint64_t bhi = MAKE_SMEM_DESC(sbase + SM_W + g2 * 32768);
                    uint64_t blo = MAKE_SMEM_DESC(sbase + SM_W + 65536 + g2 * 32768);
                    uint32_t dd = tmem + g2 * 128;
#pragma unroll
                    for (int s = 0; s < 8; s++) {
                        uint64_t ko = (s < 4) ? (uint64_t)(2 * s) : (uint64_t)(1024 + 2 * (s - 4));
                        mma_f16_ss(dd, ahi + ko, bhi + ko, LSTM_IDESC, s > 0);
                    }
#pragma unroll
                    for (int s = 0; s < 8; s++) {
                        uint64_t ko = (s < 4) ? (uint64_t)(2 * s) : (uint64_t)(1024 + 2 * (s - 4));
                        mma_f16_ss(dd, alo + ko, bhi + ko, LSTM_IDESC, true);
                    }
#pragma unroll
                    for (int s = 0; s < 8; s++) {
                        uint64_t ko = (s < 4) ? (uint64_t)(2 * s) : (uint64_t)(1024 + 2 * (s - 4));
                        mma_f16_ss(dd, ahi + ko, blo + ko, LSTM_IDESC, true);
                    }
                    // commit this gate-block's 24 MMAs to its own mbarrier
                    TCGEN05_COMMIT(sbase + (g2 ? SM_MBAR1 : SM_MBAR0));
                }
            }
        }
        // each gate-block half waits only for its own MMAs -> overlap with other half
        MBARRIER_WAIT_PARITY(mymbar, t & 1);
        TCGEN05_FENCE_AFTER();

        // epilogue: gates -> c,h ; h to conflict-free fp32 hbuf
#pragma unroll
        for (int chunk = 0; chunk < 4; chunk++) {
            uint32_t r[32];
            LDTM_X32(r, tmem + gb * 128 + chunk * 32);
            TCGEN05_WAIT_LD();
#pragma unroll
            for (int jj = 0; jj < 8; jj++) {
                int hib = chunk * 8 + jj;
                int cb = gb * 128 + chunk * 32 + jj * 4;
                float gi = __uint_as_float(r[jj * 4 + 0]) + sBias[cb + 0];
                float gf = __uint_as_float(r[jj * 4 + 1]) + sBias[cb + 1];
                float gg = __uint_as_float(r[jj * 4 + 2]) + sBias[cb + 2];
                float go = __uint_as_float(r[jj * 4 + 3]) + sBias[cb + 3];
                float cc = siga(gf) * cR[hib] + siga(gi) * tanha(gg);
                cR[hib] = cc;
                float hv = siga(go) * tanha(cc);
                hbuf[bloc * 65 + (gb << 5) + hib] = hv;
            }
        }
        __syncthreads();  // hbuf complete AND both mbarriers fired -> all MMAs done

        // prefetch x(t+1): safe now (all MMAs done reading atom-col 0)
        if (t < 4) {
            size_t xb = ((size_t)(i * 5 + t + 1) * 32 + bx) * 8192;
            const char* xh = (const char*)(d_xhi + xb);
            const char* xl = (const char*)(d_xlo + xb);
#pragma unroll
            for (int j = 0; j < 4; j++) {
                int ch = (tid + j * 256) * 16;
                cpa16(smem + SM_AHI + ch, xh + ch);
                cpa16(smem + SM_ALO + ch, xl + ch);
            }
            asm volatile("cp.async.commit_group;");

            // reshape: hbuf -> swizzled bf16 hi/lo h atoms (STS.128, conflict-free)
#pragma unroll
            for (int u = 0; u < 4; u++) {
                int unit = tid + u * 256;
                int row = unit >> 3, cg = unit & 7;
                const float* hp = hbuf + row * 65 + cg * 8;
                uint32_t hi4[4], lo4[4];
#pragma unroll
                for (int p = 0; p < 4; p++) {
                    float v0 = hp[2 * p], v1 = hp[2 * p + 1];
                    __nv_bfloat16 h0b = __float2bfloat16(v0);
                    __nv_bfloat16 h1b = __float2bfloat16(v1);
                    __nv_bfloat162 hh;
                    hh.x = h0b;
                    hh.y = h1b;
                    hi4[p] = *(uint32_t*)&hh;
                    __nv_bfloat162 ll;
                    ll.x = __float2bfloat16(v0 - __bfloat162float(h0b));
                    ll.y = __float2bfloat16(v1 - __bfloat162float(h1b));
                    lo4[p] = *(uint32_t*)&ll;
                }
                uint32_t off = ((uint32_t)(row >> 3) + 16u) * 1024u +
                               (uint32_t)(row & 7) * 128u + (uint32_t)cg * 16u;
                uint32_t sw = swz128(off);
                *(uint4*)(smem + SM_AHI + sw) = make_uint4(hi4[0], hi4[1], hi4[2], hi4[3]);
                *(uint4*)(smem + SM_ALO + sw) = make_uint4(lo4[0], lo4[1], lo4[2], lo4[3]);
            }
        }
        TCGEN05_FENCE_BEFORE();
    }

    __syncthreads();
    if (wid == 0) TCGEN05_DEALLOC(tmem, 256);

    float* sP = (float*)(smem + SM_W);
    for (int idx = tid; idx < 4096; idx += 256) {
        int e = idx >> 6, h = idx & 63;
        sP[h * 65 + e] = w_l[(size_t)i * 4096 + idx];
    }
    __syncthreads();

    int bp = tid >> 1;
    int e0 = (tid & 1) * 32;
    float acc[32];
#pragma unroll
    for (int e = 0; e < 32; e++) acc[e] = b_l[i * 64 + e0 + e];
#pragma unroll 8
    for (int h = 0; h < 64; h++) {
        float hv = hbuf[bp * 65 + h];
#pragma unroll
        for (int e = 0; e < 32; e++) acc[e] = fmaf(sP[h * 65 + e0 + e], hv, acc[e]);
    }
    float* dst = d_feat + (size_t)(b0 + bp) * 448 + 64 + i * 64 + e0;
#pragma unroll
    for (int e = 0; e < 32; e++) dst[e] = tanhfast(acc[e]);
#endif  // HAS_TCGEN05
}

// ================= fp32 fallback LSTM =================
#define LSTM_SMEM_FLOATS (32768 + 2 * 8192 + 8192 + 256)
#define SXOFF 32768
#define SHOFF (32768 + 16384)
#define SBOFF (32768 + 16384 + 8192)

__device__ __forceinline__ void gemm_half(u64t acc[8][4], const float* __restrict__ vbase,
                                          const ulonglong2* __restrict__ sWp, int k0,
                                          int hc, int btb) {
#pragma unroll 4
    for (int kc = 0; kc < 32; kc++) {
        float2 vv[8];
#pragma unroll
        for (int bb = 0; bb < 8; bb++)
            vv[bb] = *(const float2*)(vbase + (btb + bb) * 64 + kc * 2);
#pragma unroll
        for (int kk = 0; kk < 2; kk++) {
            int k = k0 + kc * 2 + kk;
            ulonglong2 wlo = sWp[k * 64 + hc];
            ulonglong2 whi = sWp[k * 64 + 32 + hc];
#pragma unroll
            for (int bb = 0; bb < 8; bb++) {
                u64t vp = pk2(kk ? vv[bb].y : vv[bb].x);
                fma2(acc[bb][0], wlo.x, vp);
                fma2(acc[bb][1], wlo.y, vp);
                fma2(acc[bb][2], whi.x, vp);
                fma2(acc[bb][3], whi.y, vp);
            }
        }
    }
}

__global__ void __launch_bounds__(512, 1) lstm_fp32_kernel(const float* __restrict__ h0,
                                                           const float* __restrict__ c0,
                                                           const float* __restrict__ w_l,
                                                           const float* __restrict__ b_l) {
    if (d_useTC) return;
    extern __shared__ float sm[];
    float* sW = sm;
    float* sX = sm + SXOFF;
    float* sH = sm + SHOFF;
    float* sB = sm + SBOFF;
    int tid = threadIdx.x;
    int i = blockIdx.y;
    int b0 = blockIdx.x * 128;
    int hc = tid & 31;
    int btb = (tid >> 5) * 8;

    const float* wt = d_Wt + i * 32768;
#pragma unroll
    for (int j = 0; j < 16; j++) cpa16(sW + (tid + j * 512) * 4, wt + (tid + j * 512) * 4);
    {
        const float* mp = d_means + ((size_t)(5 * i + 0) * BATCH + b0) * 64;
        const float* hp = h0 + ((size_t)i * BATCH + b0) * 64;
#pragma unroll
        for (int j = 0; j < 4; j++) {
            int ch = tid + j * 512;
            cpa16(sX + ch * 4, mp + ch * 4);
            cpa16(sH + ch * 4, hp + ch * 4);
        }
    }
    asm volatile("cp.async.commit_group;");
    {
        const float* mp = d_means + ((size_t)(5 * i + 1) * BATCH + b0) * 64;
#pragma unroll
        for (int j = 0; j < 4; j++) {
            int ch = tid + j * 512;
            cpa16(sX + 8192 + ch * 4, mp + ch * 4);
        }
    }
    asm volatile("cp.async.commit_group;");

    if (tid < 256) sB[tid] = d_bias[i * 256 + tid];

    float cR[8][2];
#pragma unroll
    for (int bb = 0; bb < 8; bb++)
#pragma unroll
        for (int hp = 0; hp < 2; hp++)
            cR[bb][hp] = c0[((size_t)i * BATCH + b0 + btb + bb) * 64 + hc + hp * 32];

    const ulonglong2* sWp = (const ulonglong2*)sW;
    const ulonglong2* sBp = (const ulonglong2*)sB;

    for (int t = 0; t < 5; t++) {
        if (t < 4)
            asm volatile("cp.async.wait_group 1;");
        else
            asm volatile("cp.async.wait_group 0;");
        __syncthreads();

        u64t acc[8][4];
        {
            ulonglong2 bp0 = sBp[hc];
            ulonglong2 bp1 = sBp[32 + hc];
#pragma unroll
            for (int bb = 0; bb < 8; bb++) {
                acc[bb][0] = bp0.x;
                acc[bb][1] = bp0.y;
                acc[bb][2] = bp1.x;
                acc[bb][3] = bp1.y;
            }
        }
        gemm_half(acc, sX + (t & 1) * 8192, sWp, 0, hc, btb);
        gemm_half(acc, sH, sWp, 64, hc, btb);
        __syncthreads();

        if (t + 2 <= 4) {
            const float* mp = d_means + ((size_t)(5 * i + t + 2) * BATCH + b0) * 64;
#pragma unroll
            for (int j = 0; j < 4; j++) {
                int ch = tid + j * 512;
                cpa16(sX + (t & 1) * 8192 + ch * 4, mp + ch * 4);
            }
            asm volatile("cp.async.commit_group;");
        }

#pragma unroll
        for (int bb = 0; bb < 8; bb++) {
            int b = btb + bb;
#pragma unroll
            for (int hp = 0; hp < 2; hp++) {
                float gi, gf, gg, go;
                up2(acc[bb][hp * 2], gi, gf);
                up2(acc[bb][hp * 2 + 1], gg, go);
                float cc = sigf(gf) * cR[bb][hp] + sigf(gi) * tanhfast(gg);
                cR[bb][hp] = cc;
                sH[b * 64 + hc + hp * 32] = sigf(go) * tanhfast(cc);
            }
        }
    }
    __syncthreads();

    float* sP = sX;
    const float* wl = w_l + (size_t)i * 64 * 64;
    for (int idx = tid; idx < 4096; idx += 512) {
        int e = idx >> 6, h = idx & 63;
        sP[h * 65 + e] = wl[idx];
    }
    __syncthreads();

    float accp[8][2];
    {
        float bl0 = b_l[i * 64 + hc];
        float bl1 = b_l[i * 64 + 32 + hc];
#pragma unroll
        for (int bb = 0; bb < 8; bb++) {
            accp[bb][0] = bl0;
            accp[bb][1] = bl1;
        }
    }
#pragma unroll 8
    for (int h = 0; h < 64; h++) {
        float w0 = sP[h * 65 + hc];
        float w1 = sP[h * 65 + 32 + hc];
#pragma unroll
        for (int bb = 0; bb < 8; bb++) {
            float hv = sH[(btb + bb) * 64 + h];
            accp[bb][0] = fmaf(w0, hv, accp[bb][0]);
            accp[bb][1] = fmaf(w1, hv, accp[bb][1]);
        }
    }
#pragma unroll
    for (int bb = 0; bb < 8; bb++) {
        size_t base = (size_t)(b0 + btb + bb) * 448 + 64 + i * 64;
        d_feat[base + hc] = tanhfast(accp[bb][0]);
        d_feat[base + 32 + hc] = tanhfast(accp[bb][1]);
    }
}

// ---------------- final combine ----------------
#define FINAL_SMEM_FLOATS (81 * 64 + 448 * 64 + 128 * 64 + 256)

__global__ void __launch_bounds__(256) final_kernel(
    const float* __restrict__ x, const float* __restrict__ dw_b,
    float* __restrict__ out) {
    extern __shared__ float sm[];
    float* swide2 = sm;
    float* scq2 = sm + 81 * 64;
    float* scqu2 = sm + 81 * 64 + 448 * 64;
    float* sb2 = scqu2 + 128 * 64;
    int tid = threadIdx.x;
    for (int idx = tid; idx < 81 * 32; idx += 256)
        ((float2*)swide2)[idx] = d_wideT[idx];
    for (int idx = tid; idx < 448 * 32; idx += 256)
        ((float2*)scq2)[idx] = d_cqT[idx];
    for (int idx = tid; idx < 128 * 32; idx += 256)
        ((float2*)scqu2)[idx] = d_cquT[idx];
    if (tid < 128) ((float2*)sb2)[tid] = d_headB[tid];
    __syncthreads();

    const u64t* swide2u = (const u64t*)swide2;
    const u64t* scq2u = (const u64t*)scq2;
    const u64t* scqu2u = (const u64t*)scqu2;
    const u64t* sb2u = (const u64t*)sb2;

    int warp = tid >> 5, lane = tid & 31;
    float dwb0 = __ldg(dw_b);
    int bstart = blockIdx.x * 32 + warp * 4;

    u64t aw[4];
    {
        u64t bw = sb2u[lane];
#pragma unroll
        for (int t = 0; t < 4; t++) aw[t] = bw;
    }
#pragma unroll 3
    for (int j = 0; j < 81; j++) {
        float4 xv = __ldg((const float4*)(x + (size_t)j * BATCH + bstart));
        u64t w2 = swide2u[j * 32 + lane];
        fma2(aw[0], w2, pk2(xv.x));
        fma2(aw[1], w2, pk2(xv.y));
        fma2(aw[2], w2, pk2(xv.z));
        fma2(aw[3], w2, pk2(xv.w));
    }
    float w0[4], w1[4];
#pragma unroll
    for (int t = 0; t < 4; t++) {
        float a, b;
        up2(aw[t], a, b);
        w0[t] = tanhfast(a);
        w1[t] = tanhfast(b);
    }

    u64t aq[4];
    {
        u64t bq = sb2u[32 + lane];
#pragma unroll
        for (int t = 0; t < 4; t++) aq[t] = bq;
    }
#pragma unroll 2
    for (int j4 = 0; j4 < 112; j4++) {
        float f0[4], f1[4], f2[4], f3[4];
        *(float4*)f0 = ((const float4*)(d_feat + (size_t)(bstart + 0) * 448))[j4];
        *(float4*)f1 = ((const float4*)(d_feat + (size_t)(bstart + 1) * 448))[j4];
        *(float4*)f2 = ((const float4*)(d_feat + (size_t)(bstart + 2) * 448))[j4];
        *(float4*)f3 = ((const float4*)(d_feat + (size_t)(bstart + 3) * 448))[j4];
#pragma unroll
        for (int jj = 0; jj < 4; jj++) {
            u64t w2 = scq2u[(j4 * 4 + jj) * 32 + lane];
            fma2(aq[0], w2, pk2(f0[jj]));
            fma2(aq[1], w2, pk2(f1[jj]));
            fma2(aq[2], w2, pk2(f2[jj]));
            fma2(aq[3], w2, pk2(f3[jj]));
        }
    }
    float q0[4], q1[4];
#pragma unroll
    for (int t = 0; t < 4; t++) {
        float a, b;
        up2(aq[t], a, b);
        q0[t] = tanhfast(a);
        q1[t] = tanhfast(b);
    }

#pragma unroll
    for (int t = 0; t < 4; t++) {
        u64t a = sb2u[64 + lane];
#pragma unroll
        for (int j = 0; j < 32; j++) {
            float v = __shfl_sync(0xffffffffu, q0[t], j);
            fma2(a, scqu2u[j * 32 + lane], pk2(v));
        }
#pragma unroll
        for (int j = 0; j < 32; j++) {
            float v = __shfl_sync(0xffffffffu, q1[t], j);
            fma2(a, scqu2u[(32 + j) * 32 + lane], pk2(v));
        }
#pragma unroll
        for (int j = 0; j < 32; j++) {
            float v = __shfl_sync(0xffffffffu, w0[t], j);
            fma2(a, scqu2u[(64 + j) * 32 + lane], pk2(v));
        }
#pragma unroll
        for (int j = 0; j < 32; j++) {
            float v = __shfl_sync(0xffffffffu, w1[t], j);
            fma2(a, scqu2u[(96 + j) * 32 + lane], pk2(v));
        }
        float x0, x1;
        up2(a, x0, x1);
        float qw0 = tanhfast(x0), qw1 = tanhfast(x1);
        float d0, d1;
        up2(sb2u[96 + lane], d0, d1);
        float r = d0 * qw0 + d1 * qw1;
#pragma unroll
        for (int off = 16; off; off >>= 1) r += __shfl_xor_sync(0xffffffffu, r, off);
        if (lane == 0) out[bstart + t] = r + dwb0;
    }
}

// ---------------- launch ----------------
extern "C" void kernel_launch(void* const* d_in, const int* in_sizes, int n_in,
                              void* d_out, int out_size) {
    const float* x = (const float*)d_in[0];
    const float* emb = (const float*)d_in[1];
    const float* Wih = (const float*)d_in[2];
    const float* Whh = (const float*)d_in[3];
    const float* bih = (const float*)d_in[4];
    const float* bhh = (const float*)d_in[5];
    const float* h0 = (const float*)d_in[6];
    const float* c0 = (const float*)d_in[7];
    const float* w_l = (const float*)d_in[8];
    const float* b_l = (const float*)d_in[9];
    const float* conv1_w = (const float*)d_in[10];
    const float* conv1_b = (const float*)d_in[11];
    const float* lin1_w = (const float*)d_in[12];
    const float* lin1_b = (const float*)d_in[13];
    const float* conv2_w = (const float*)d_in[14];
    const float* conv2_b = (const float*)d_in[15];
    const float* lin2_w = (const float*)d_in[16];
    const float* lin2_b = (const float*)d_in[17];
    const float* wide_w = (const float*)d_in[18];
    const float* wide_b = (const float*)d_in[19];
    const float* cq_w = (const float*)d_in[20];
    const float* cq_b = (const float*)d_in[21];
    const float* cqu_w = (const float*)d_in[22];
    const float* cqu_b = (const float*)d_in[23];
    const float* dw_w = (const float*)d_in[24];
    const float* dw_b = (const float*)d_in[25];
    float* out = (float*)d_out;

    prep_kernel<<<760, 256>>>(Wih, Whh, bih, bhh, wide_w, wide_b, cq_w, cq_b,
                              cqu_w, cqu_b, dw_w, x);
    mean_kernel<<<(31 * 2048) / 8, 256>>>(x, emb);

    // fp32 fallback launched BEFORE the tc kernel (independent; order swap makes
    // the ncu -s window land on lstm_tc_kernel for profiling)
    cudaFuncSetAttribute(lstm_fp32_kernel, cudaFuncAttributeMaxDynamicSharedMemorySize,
                         LSTM_SMEM_FLOATS * 4);
    lstm_fp32_kernel<<<dim3(32, 4), 512, LSTM_SMEM_FLOATS * 4>>>(h0, c0, w_l, b_l);

    cudaFuncSetAttribute(lstm_tc_kernel, cudaFuncAttributeMaxDynamicSharedMemorySize,
                         TC_SMEM_BYTES);
    lstm_tc_kernel<<<148, 256, TC_SMEM_BYTES>>>(h0, c0, w_l, b_l,
                                                conv1_w, conv1_b, lin1_w, lin1_b,
                                                conv2_w, conv2_b, lin2_w, lin2_b);

    cudaFuncSetAttribute(final_kernel, cudaFuncAttributeMaxDynamicSharedMemorySize,
                         FINAL_SMEM_FLOATS * 4);
    final_kernel<<<128, 256, FINAL_SMEM_FLOATS * 4>>>(x, dw_b, out);
}

// round 15
// speedup vs baseline: 1.0894x; 1.0894x over previous
#include <cuda_runtime.h>
#include <cuda_bf16.h>
#include <math.h>
#include <cstdint>

#define BATCH 4096

#if defined(__CUDA_ARCH_FEAT_SM103_ALL) || defined(__CUDA_ARCH_FEAT_SM100_ALL)
#define HAS_TCGEN05 1
#else
#define HAS_TCGEN05 0
#endif

// ---------------- scratch (device globals; no allocation allowed) ----------------
__device__ int d_useTC;
__device__ int d_cntp[31 * 8];
__device__ __align__(256) float d_means[30 * BATCH * 64];
__device__ __align__(256) float d_feat[BATCH * 448];
__device__ __align__(256) float d_Wt[4 * 128 * 256];          // fp32 path
__device__ float d_bias[4 * 256];                             // fp32 path
__device__ __align__(256) __nv_bfloat16 d_Whi[4 * 2 * 16384]; // tc path
__device__ __align__(256) __nv_bfloat16 d_Wlo[4 * 2 * 16384];
__device__ float d_biasI[4 * 256];
__device__ __align__(256) __nv_bfloat16 d_xhi[20 * 32 * 8192];
__device__ __align__(256) __nv_bfloat16 d_xlo[20 * 32 * 8192];
__device__ __align__(256) float2 d_wideT[81 * 32];
__device__ __align__(256) float2 d_cqT[448 * 32];
__device__ __align__(256) float2 d_cquT[128 * 32];
__device__ __align__(256) float2 d_headB[4 * 32];

__constant__ int c_gstart[31] = {
    276,
    211, 224, 237, 250, 263,
    662, 672, 682, 692, 702,
    612, 622, 632, 642, 652,
    397, 410, 423, 436, 449,
    512, 522, 532, 542, 552,
    862, 872, 882, 892, 902};
__constant__ int c_grows[31] = {
    10,
    10, 10, 10, 10, 10,
    5, 5, 5, 5, 5,
    5, 5, 5, 5, 5,
    10, 10, 10, 10, 10,
    5, 5, 5, 5, 5,
    5, 5, 5, 5, 5};

__device__ __forceinline__ float sigf(float x) { return 1.0f / (1.0f + __expf(-x)); }
__device__ __forceinline__ float tanhfast(float x) {
    return fmaf(2.0f, 1.0f / (1.0f + __expf(-2.0f * x)), -1.0f);
}
__device__ __forceinline__ float tanha(float x) {
    float y;
    asm("tanh.approx.f32 %0, %1;" : "=f"(y) : "f"(x));
    return y;
}
__device__ __forceinline__ float siga(float x) {
    return fmaf(0.5f, tanha(0.5f * x), 0.5f);
}
__device__ __forceinline__ void cpa16(void* dst, const void* src) {
    unsigned a = (unsigned)__cvta_generic_to_shared(dst);
    asm volatile("cp.async.cg.shared.global [%0], [%1], 16;" ::"r"(a), "l"(src));
}
__device__ __forceinline__ uint32_t smem_u32(const void* p) {
    return (uint32_t)__cvta_generic_to_shared(p);
}
static __device__ __forceinline__ uint32_t swz128(uint32_t off) {
    return off ^ ((off >> 3) & 0x70);
}
typedef unsigned long long u64t;
__device__ __forceinline__ void fma2(u64t& d, u64t a, u64t b) {
    asm("fma.rn.f32x2 %0, %1, %2, %0;" : "+l"(d) : "l"(a), "l"(b));
}
__device__ __forceinline__ u64t pk2(float v) {
    u64t r;
    asm("mov.b64 %0, {%1, %1};" : "=l"(r) : "f"(v));
    return r;
}
__device__ __forceinline__ void up2(u64t v, float& lo, float& hi) {
    asm("mov.b64 {%0, %1}, %2;" : "=f"(lo), "=f"(hi) : "l"(v));
}
__device__ __forceinline__ uint32_t bf2pack(float a, float b) {
    __nv_bfloat162 h;
    h.x = __float2bfloat16(a);
    h.y = __float2bfloat16(b);
    return *(uint32_t*)&h;
}

// -------- bulk-copy + mbarrier (final_kernel only this round) --------
__device__ __forceinline__ void cpbulk(uint32_t dst_smem, const void* src,
                                       uint32_t bytes, uint32_t mbar) {
    asm volatile(
        "cp.async.bulk.shared::cta.global.mbarrier::complete_tx::bytes [%0], [%1], %2, [%3];"
        :: "r"(dst_smem), "l"(src), "r"(bytes), "r"(mbar)
        : "memory");
}
#define MBARRIER_INIT(mb, n) \
    asm volatile("mbarrier.init.shared.b64 [%0], %1;" ::"r"(mb), "r"(n) : "memory")
#define MBARRIER_EXPECT_TX(mb, bytes) \
    asm volatile("mbarrier.arrive.expect_tx.shared.b64 _, [%0], %1;" ::"r"(mb), "r"(bytes) : "memory")
#define MBARRIER_WAIT_PARITY(mb, ph) do { \
    uint32_t _mb = (mb), _p = (ph), _done; \
    asm volatile("{\n\t.reg .pred p;\n\tmbarrier.try_wait.parity.acquire.cta.shared::cta.b64 p, [%1], %2;\n\tselp.b32 %0, 1, 0, p;\n\t}" \
        : "=r"(_done) : "r"(_mb), "r"(_p) : "memory"); \
    if (!_done) { \
        asm volatile("{\n\t.reg .pred P1;\n\tWL_%=:\n\tmbarrier.try_wait.parity.acquire.cta.shared::cta.b64 P1, [%0], %1, 0x989680;\n\t@P1 bra.uni WD_%=;\n\tbra.uni WL_%=;\n\tWD_%=:\n\t}" \
            :: "r"(_mb), "r"(_p) : "memory"); \
    } \
} while (0)

// ---------------- prep + count fused ----------------
__global__ void prep_kernel(const float* __restrict__ Wih, const float* __restrict__ Whh,
                            const float* __restrict__ bih, const float* __restrict__ bhh,
                            const float* __restrict__ wide_w, const float* __restrict__ wide_b,
                            const float* __restrict__ cq_w, const float* __restrict__ cq_b,
                            const float* __restrict__ cqu_w, const float* __restrict__ cqu_b,
                            const float* __restrict__ dw_w, const float* __restrict__ x) {
    if (blockIdx.x >= 512) {
        int cb = blockIdx.x - 512;
        int g = cb >> 3;
        int part = cb & 7;
        int n = c_grows[g] * BATCH;
        const float* p = x + (size_t)c_gstart[g] * BATCH;
        int cnt = 0;
        for (int i = part * 256 + threadIdx.x; i < n; i += 2048) cnt += (p[i] != 0.0f);
#pragma unroll
        for (int o = 16; o; o >>= 1) cnt += __shfl_xor_sync(0xffffffffu, cnt, o);
        __shared__ int wsum[8];
        if ((threadIdx.x & 31) == 0) wsum[threadIdx.x >> 5] = cnt;
        __syncthreads();
        if (threadIdx.x == 0) {
            int s = 0;
#pragma unroll
            for (int w = 0; w < 8; w++) s += wsum[w];
            d_cntp[g * 8 + part] = s;
        }
        return;
    }
    int idx = blockIdx.x * 256 + threadIdx.x;  // 131072 total
    if (idx == 0) d_useTC = HAS_TCGEN05;
#if !HAS_TCGEN05
    {
        int c = idx & 255;
        int k = (idx >> 8) & 127;
        int i = idx >> 15;
        int h = ((c & 127) >> 2) + ((c >> 7) << 5);
        int t = c & 3;
        int g = t * 64 + h;
        float v = (k < 64) ? Wih[(i * 256 + g) * 64 + k]
                           : Whh[(i * 256 + g) * 64 + (k - 64)];
        d_Wt[idx] = v;
    }
    if (idx < 1024) {
        int i = idx >> 8;
        int c = idx & 255;
        int h = ((c & 127) >> 2) + ((c >> 7) << 5);
        int t = c & 3;
        int g = i * 256 + t * 64 + h;
        d_bias[idx] = bih[g] + bhh[g];
    }
#else
    {
        int i = idx >> 15;
        int rem = idx & 32767;
        int gb = rem >> 14;
        int rem2 = rem & 16383;
        int n = rem2 >> 7;
        int k = rem2 & 127;
        int t = n & 3;
        int hib = n >> 2;
        int g = t * 64 + 32 * gb + hib;
        float v = (k < 64) ? Wih[(i * 256 + g) * 64 + k]
                           : Whh[(i * 256 + g) * 64 + (k - 64)];
        __nv_bfloat16 hi = __float2bfloat16(v);
        __nv_bfloat16 lo = __float2bfloat16(v - __bfloat162float(hi));
        uint32_t off = ((uint32_t)(n >> 3) + ((uint32_t)(k >> 6) << 4)) * 1024u +
                       (uint32_t)(n & 7) * 128u + (uint32_t)(k & 63) * 2u;
        uint32_t sw = swz128(off) >> 1;
        int tile = i * 2 + gb;
        d_Whi[tile * 16384 + sw] = hi;
        d_Wlo[tile * 16384 + sw] = lo;
    }
    if (idx < 1024) {
        int i = idx >> 8;
        int c = idx & 255;
        int gb = c >> 7;
        int hib = (c & 127) >> 2;
        int t = c & 3;
        int src = i * 256 + t * 64 + 32 * gb + hib;
        d_biasI[idx] = bih[src] + bhh[src];
    }
#endif
    if (idx < 14336) {
        int j = idx >> 5, o = idx & 31;
        d_cqT[idx] = make_float2(cq_w[o * 448 + j], cq_w[(o + 32) * 448 + j]);
    }
    if (idx < 4096) {
        int j = idx >> 5, o = idx & 31;
        d_cquT[idx] = make_float2(cqu_w[o * 128 + j], cqu_w[(o + 32) * 128 + j]);
    }
    if (idx < 2592) {
        int j = idx >> 5, o = idx & 31;
        d_wideT[idx] = make_float2(wide_w[o * 81 + j], wide_w[(o + 32) * 81 + j]);
    }
    if (idx < 32) {
        d_headB[idx] = make_float2(wide_b[idx], wide_b[idx + 32]);
        d_headB[32 + idx] = make_float2(cq_b[idx], cq_b[idx + 32]);
        d_headB[64 + idx] = make_float2(cqu_b[idx], cqu_b[idx + 32]);
        d_headB[96 + idx] = make_float2(dw_w[idx], dw_w[idx + 32]);
    }
}

// ---------------- gathers + means ----------------
__global__ void mean_kernel(const float* __restrict__ x, const float* __restrict__ emb) {
    int w = blockIdx.x * 8 + (threadIdx.x >> 5);
    int lane = threadIdx.x & 31;
    int half = lane >> 4;
    int li = lane & 15;
    int g = w >> 11;
    int bp = w & 2047;
    int b = bp * 2 + half;

    int cpart = (lane < 8) ? d_cntp[g * 8 + lane] : 0;
#pragma unroll
    for (int o = 4; o; o >>= 1) cpart += __shfl_xor_sync(0xffffffffu, cpart, o);
    cpart = __shfl_sync(0xffffffffu, cpart, 0);
    float L = fminf(fmaxf((float)cpart, 1.0f), (float)c_grows[g]);
    int Lu = (int)(L + 0.5f);

    const float* xcol = x + (size_t)c_gstart[g] * BATCH + b;
    int tokr = 0;
    if (li < Lu) tokr = (int)xcol[(size_t)li * BATCH];

    float a0 = 0.0f, a1 = 0.0f, a2 = 0.0f, a3 = 0.0f;
    const float4* emb4 = (const float4*)emb;
#pragma unroll
    for (int r = 0; r < 10; r++) {
        if (r < Lu) {
            int tok = __shfl_sync(0xffffffffu, tokr, (lane & 16) + r);
            float4 v = __ldg(emb4 + (size_t)tok * 16 + li);
            a0 += v.x;
            a1 += v.y;
            a2 += v.z;
            a3 += v.w;
        }
    }
    float inv = 1.0f / L;
    a0 *= inv; a1 *= inv; a2 *= inv; a3 *= inv;

    if (g == 0) {
        ((float4*)(d_feat + (size_t)b * 448))[li] = make_float4(a0, a1, a2, a3);
    } else if (g <= 20 && d_useTC) {
        int row = b & 127;
        int tile = b >> 7;
        uint32_t off = (uint32_t)(row >> 3) * 1024u + (uint32_t)(row & 7) * 128u +
                       (uint32_t)li * 8u;
        uint32_t sw = swz128(off);
        uint32_t hi01 = bf2pack(a0, a1);
        uint32_t hi23 = bf2pack(a2, a3);
        __nv_bfloat16 h0 = __float2bfloat16(a0), h1 = __float2bfloat16(a1);
        __nv_bfloat16 h2 = __float2bfloat16(a2), h3 = __float2bfloat16(a3);
        uint32_t lo01 = bf2pack(a0 - __bfloat162float(h0), a1 - __bfloat162float(h1));
        uint32_t lo23 = bf2pack(a2 - __bfloat162float(h2), a3 - __bfloat162float(h3));
        size_t base = ((size_t)(g - 1) * 32 + tile) * 8192;
        *(u64t*)((char*)(d_xhi + base) + sw) = (u64t)hi01 | ((u64t)hi23 << 32);
        *(u64t*)((char*)(d_xlo + base) + sw) = (u64t)lo01 | ((u64t)lo23 << 32);
    } else {
        ((float4*)(d_means + ((size_t)(g - 1) * BATCH + b) * 64))[li] =
            make_float4(a0, a1, a2, a3);
    }
}

// ================= fused LSTM(tc) + CNN kernel (proven cp.async staging) ==========
#define SM_AHI 0
#define SM_ALO 32768
#define SM_W 65536
#define SM_BIAS 196608
#define SM_PTR 197632
#define SM_MBAR0 197640
#define SM_MBAR1 197648
#define SM_HBUF 197664          // 128*65 floats
#define TC_SMEM_BYTES (197664 + 33280)

#if HAS_TCGEN05
static constexpr uint64_t SMEM_DESC_BASE_SW128 =
    (uint64_t(2) << 61) | (uint64_t(1) << 46) | (uint64_t(64) << 32) | (uint64_t(1) << 16);
#define MAKE_SMEM_DESC(base_addr) \
    (SMEM_DESC_BASE_SW128 | ((uint64_t)((base_addr) >> 4) & 0x3FFF))
#define LSTM_IDESC 0x8200490u

__device__ __forceinline__ uint32_t elect_one_pred() {
    uint32_t pred;
    asm volatile(
        "{\n\t.reg .pred p;\n\telect.sync _|p, 0xFFFFFFFF;\n\tselp.b32 %0, 1, 0, p;\n\t}"
        : "=r"(pred));
    return pred;
}
__device__ __forceinline__ void mma_f16_ss(uint32_t d, uint64_t a, uint64_t b,
                                           uint32_t idesc, bool accum) {
    uint32_t en = accum ? 1u : 0u;
    asm volatile(
        "{\n\t"
        ".reg .pred p;\n\t"
        "setp.ne.u32 p, %4, 0;\n\t"
        "tcgen05.mma.cta_group::1.kind::f16 [%0], %1, %2, %3, {%5, %5, %5, %5}, p;\n\t"
        "}"
        :: "r"(d), "l"(a), "l"(b), "r"(idesc), "r"(en), "r"(0u)
        : "memory");
}
#define TCGEN05_ALLOC(sa, n) \
    asm volatile("tcgen05.alloc.cta_group::1.sync.aligned.shared::cta.b32 [%0], %1;" ::"r"(sa), "r"(n) : "memory")
#define TCGEN05_DEALLOC(t, n) \
    asm volatile("tcgen05.dealloc.cta_group::1.sync.aligned.b32 %0, %1;" ::"r"(t), "r"(n))
#define TCGEN05_RELINQ() \
    asm volatile("tcgen05.relinquish_alloc_permit.cta_group::1.sync.aligned;")
#define TCGEN05_COMMIT(mb) \
    asm volatile("tcgen05.commit.cta_group::1.mbarrier::arrive::one.shared::cluster.b64 [%0];" ::"r"(mb) : "memory")
#define TCGEN05_FENCE_BEFORE() asm volatile("tcgen05.fence::before_thread_sync;" ::: "memory")
#define TCGEN05_FENCE_AFTER() asm volatile("tcgen05.fence::after_thread_sync;" ::: "memory")
#define TCGEN05_WAIT_LD() asm volatile("tcgen05.wait::ld.sync.aligned;" ::: "memory")
#define FENCE_PROXY_ASYNC() asm volatile("fence.proxy.async.shared::cta;" ::: "memory")
#define LDTM_X32(r, addr) \
    asm volatile( \
        "tcgen05.ld.sync.aligned.32x32b.x32.b32 " \
        "{%0, %1, %2, %3, %4, %5, %6, %7, %8, %9, %10, %11, %12, %13, %14, %15, " \
        " %16, %17, %18, %19, %20, %21, %22, %23, %24, %25, %26, %27, %28, %29, %30, %31}, [%32];" \
        : "=r"((r)[0]), "=r"((r)[1]), "=r"((r)[2]), "=r"((r)[3]), "=r"((r)[4]), "=r"((r)[5]), \
          "=r"((r)[6]), "=r"((r)[7]), "=r"((r)[8]), "=r"((r)[9]), "=r"((r)[10]), "=r"((r)[11]), \
          "=r"((r)[12]), "=r"((r)[13]), "=r"((r)[14]), "=r"((r)[15]), "=r"((r)[16]), "=r"((r)[17]), \
          "=r"((r)[18]), "=r"((r)[19]), "=r"((r)[20]), "=r"((r)[21]), "=r"((r)[22]), "=r"((r)[23]), \
          "=r"((r)[24]), "=r"((r)[25]), "=r"((r)[26]), "=r"((r)[27]), "=r"((r)[28]), "=r"((r)[29]), \
          "=r"((r)[30]), "=r"((r)[31]) \
        : "r"(addr))
#endif  // HAS_TCGEN05

// cnn work for one (s, b) item
__device__ __forceinline__ void cnn_item(const float* scw, const float* slw,
                                         const float* scb, const float* slb,
                                         int s, int b) {
    float y[12][4];
#pragma unroll
    for (int o = 0; o < 12; o++)
#pragma unroll
        for (int tt = 0; tt < 4; tt++) y[o][tt] = scb[s * 12 + o];

    const float* cwp = scw + s * 1536;
    int gbase = 20 + s * 5;
    for (int e4 = 0; e4 < 16; e4++) {
        float mv[5][4];
#pragma unroll
        for (int t = 0; t < 5; t++) {
            float4 m4 = *(const float4*)(d_means + ((size_t)(gbase + t) * BATCH + b) * 64 + e4 * 4);
            mv[t][0] = m4.x; mv[t][1] = m4.y; mv[t][2] = m4.z; mv[t][3] = m4.w;
        }
#pragma unroll
        for (int ee = 0; ee < 4; ee++) {
            int e = e4 * 4 + ee;
#pragma unroll
            for (int o = 0; o < 12; o++) {
                float w0 = cwp[o * 128 + e];
                float w1 = cwp[o * 128 + 64 + e];
#pragma unroll
                for (int tt = 0; tt < 4; tt++)
                    y[o][tt] = fmaf(mv[tt][ee], w0, fmaf(mv[tt + 1][ee], w1, y[o][tt]));
            }
        }
    }
    float p[24];
#pragma unroll
    for (int o = 0; o < 12; o++) {
#pragma unroll
        for (int j = 0; j < 2; j++)
            p[j * 12 + o] = fmaxf(fmaxf(y[o][2 * j], y[o][2 * j + 1]), 0.0f);
    }
    const float* lwp = slw + s * 1536;
    float* dst = d_feat + (size_t)b * 448 + 320 + s * 64;
    for (int eo = 0; eo < 64; eo++) {
        float acc = slb[s * 64 + eo];
#pragma unroll
        for (int j = 0; j < 24; j++) acc = fmaf(lwp[eo * 24 + j], p[j], acc);
        dst[eo] = fmaxf(acc, 0.0f);
    }
}

__global__ void __launch_bounds__(256, 1) lstm_tc_kernel(
    const float* __restrict__ h0, const float* __restrict__ c0,
    const float* __restrict__ w_l, const float* __restrict__ b_l,
    const float* __restrict__ cw1, const float* __restrict__ cb1,
    const float* __restrict__ lw1, const float* __restrict__ lb1,
    const float* __restrict__ cw2, const float* __restrict__ cb2,
    const float* __restrict__ lw2, const float* __restrict__ lb2) {
    extern __shared__ __align__(1024) char smem[];
    int tid = threadIdx.x;

    if (blockIdx.x >= 128) {
        // ---- CNN blocks (both arch paths) ----
        float* scw = (float*)smem;
        float* slw = scw + 3072;
        float* scb = slw + 3072;
        float* slb = scb + 32;
        for (int idx = tid; idx < 1536; idx += 256) {
            scw[idx] = cw1[idx];
            scw[1536 + idx] = cw2[idx];
            slw[idx] = lw1[idx];
            slw[1536 + idx] = lw2[idx];
        }
        if (tid < 12) {
            scb[tid] = cb1[tid];
            scb[12 + tid] = cb2[tid];
        }
        if (tid < 64) {
            slb[tid] = lb1[tid];
            slb[64 + tid] = lb2[tid];
        }
        __syncthreads();
        for (int item = (blockIdx.x - 128) * 256 + tid; item < 8192; item += 5120) {
            int s = item >> 12;
            int b = item & 4095;
            cnn_item(scw, slw, scb, slb, s, b);
        }
        return;
    }

#if HAS_TCGEN05
    uint32_t sbase = smem_u32(smem);
    int wid = tid >> 5;
    int lane = tid & 31;
    int i = blockIdx.x >> 5;
    int bx = blockIdx.x & 31;
    int b0 = bx * 128;

    if (wid == 0) {
        TCGEN05_ALLOC(sbase + SM_PTR, 256);
    } else {
        TCGEN05_RELINQ();
    }

    {
        const char* whi = (const char*)(d_Whi + (size_t)i * 2 * 16384);
        const char* wlo = (const char*)(d_Wlo + (size_t)i * 2 * 16384);
#pragma unroll
        for (int j = 0; j < 16; j++) {
            int ch = (tid + j * 256) * 16;
            cpa16(smem + SM_W + ch, whi + ch);
            cpa16(smem + SM_W + 65536 + ch, wlo + ch);
        }
        size_t xb = ((size_t)(i * 5) * 32 + bx) * 8192;
        const char* xh = (const char*)(d_xhi + xb);
        const char* xl = (const char*)(d_xlo + xb);
#pragma unroll
        for (int j = 0; j < 4; j++) {
            int ch = (tid + j * 256) * 16;
            cpa16(smem + SM_AHI + ch, xh + ch);
            cpa16(smem + SM_ALO + ch, xl + ch);
        }
    }
    asm volatile("cp.async.commit_group;");

    __syncthreads();
    uint32_t tmem;
    asm volatile("ld.shared.b32 %0, [%1];" : "=r"(tmem) : "r"(sbase + SM_PTR));

    for (int idx = tid; idx < 8192; idx += 256) {
        int row = idx >> 6, col = idx & 63;
        float v = h0[((size_t)(i << 12) + b0 + row) * 64 + col];
        __nv_bfloat16 hi = __float2bfloat16(v);
        __nv_bfloat16 lo = __float2bfloat16(v - __bfloat162float(hi));
        uint32_t off = ((uint32_t)(row >> 3) + 16u) * 1024u + (uint32_t)(row & 7) * 128u +
                       (uint32_t)col * 2u;
        uint32_t sw = swz128(off);
        *(__nv_bfloat16*)(smem + SM_AHI + sw) = hi;
        *(__nv_bfloat16*)(smem + SM_ALO + sw) = lo;
    }
    float* sBias = (float*)(smem + SM_BIAS);
    sBias[tid] = d_biasI[i * 256 + tid];

    int gb = wid >> 2;
    int bloc = ((wid & 3) << 5) + lane;
    uint32_t mymbar = sbase + (gb ? SM_MBAR1 : SM_MBAR0);

    float cR[32];
    {
        const float4* cp4 =
            (const float4*)(c0 + ((size_t)(i << 12) + b0 + bloc) * 64 + (gb << 5));
#pragma unroll
        for (int q = 0; q < 8; q++) {
            float4 v = cp4[q];
            cR[q * 4 + 0] = v.x;
            cR[q * 4 + 1] = v.y;
            cR[q * 4 + 2] = v.z;
            cR[q * 4 + 3] = v.w;
        }
    }

    if (tid == 0) {
        MBARRIER_INIT(sbase + SM_MBAR0, 1);
        MBARRIER_INIT(sbase + SM_MBAR1, 1);
    }
    __syncthreads();

    float* hbuf = (float*)(smem + SM_HBUF);

    for (int t = 0; t < 5; t++) {
        asm volatile("cp.async.wait_group 0;");
        __syncthreads();
        FENCE_PROXY_ASYNC();

        if (wid == 0) {
            TCGEN05_FENCE_AFTER();
            if (elect_one_pred()) {
                uint64_t ahi = MAKE_SMEM_DESC(sbase + SM_AHI);
                uint64_t alo = MAKE_SMEM_DESC(sbase + SM_ALO);
#pragma unroll
                for (int g2 = 0; g2 < 2; g2++) {
                    uint64_t bhi = MAKE_SMEM_DESC(sbase + SM_W + g2 * 32768);
                    uint64_t blo = MAKE_SMEM_DESC(sbase + SM_W + 65536 + g2 * 32768);
                    uint32_t dd = tmem + g2 * 128;
#pragma unroll
                    for (int s = 0; s < 8; s++) {
                        uint64_t ko = (s < 4) ? (uint64_t)(2 * s) : (uint64_t)(1024 + 2 * (s - 4));
                        mma_f16_ss(dd, ahi + ko, bhi + ko, LSTM_IDESC, s > 0);
                    }
#pragma unroll
                    for (int s = 0; s < 8; s++) {
                        uint64_t ko = (s < 4) ? (uint64_t)(2 * s) : (uint64_t)(1024 + 2 * (s - 4));
                        mma_f16_ss(dd, alo + ko, bhi + ko, LSTM_IDESC, true);
                    }
#pragma unroll
                    for (int s = 0; s < 8; s++) {
                        uint64_t ko = (s < 4) ? (uint64_t)(2 * s) : (uint64_t)(1024 + 2 * (s - 4));
                        mma_f16_ss(dd, ahi + ko, blo + ko, LSTM_IDESC, true);
                    }
                    TCGEN05_COMMIT(sbase + (g2 ? SM_MBAR1 : SM_MBAR0));
                }
            }
        }
        MBARRIER_WAIT_PARITY(mymbar, t & 1);
        TCGEN05_FENCE_AFTER();

        // epilogue: gates -> c,h ; h to conflict-free fp32 hbuf
#pragma unroll
        for (int chunk = 0; chunk < 4; chunk++) {
            uint32_t r[32];
            LDTM_X32(r, tmem + gb * 128 + chunk * 32);
            TCGEN05_WAIT_LD();
#pragma unroll
            for (int jj = 0; jj < 8; jj++) {
                int hib = chunk * 8 + jj;
                int cb = gb * 128 + chunk * 32 + jj * 4;
                float gi = __uint_as_float(r[jj * 4 + 0]) + sBias[cb + 0];
                float gf = __uint_as_float(r[jj * 4 + 1]) + sBias[cb + 1];
                float gg = __uint_as_float(r[jj * 4 + 2]) + sBias[cb + 2];
                float go = __uint_as_float(r[jj * 4 + 3]) + sBias[cb + 3];
                float cc = siga(gf) * cR[hib] + siga(gi) * tanha(gg);
                cR[hib] = cc;
                float hv = siga(go) * tanha(cc);
                hbuf[bloc * 65 + (gb << 5) + hib] = hv;
            }
        }
        __syncthreads();  // hbuf complete AND both mma mbars fired -> all MMAs done

        if (t < 4) {
            // prefetch x(t+1) via cp.async (safe: all MMAs done reading atom-col 0)
            size_t xb = ((size_t)(i * 5 + t + 1) * 32 + bx) * 8192;
            const char* xh = (const char*)(d_xhi + xb);
            const char* xl = (const char*)(d_xlo + xb);
#pragma unroll
            for (int j = 0; j < 4; j++) {
                int ch = (tid + j * 256) * 16;
                cpa16(smem + SM_AHI + ch, xh + ch);
                cpa16(smem + SM_ALO + ch, xl + ch);
            }
            asm volatile("cp.async.commit_group;");

            // reshape: hbuf -> swizzled bf16 hi/lo h atoms (STS.128, conflict-free)
#pragma unroll
            for (int u = 0; u < 4; u++) {
                int unit = tid + u * 256;
                int row = unit >> 3, cg = unit & 7;
                const float* hp = hbuf + row * 65 + cg * 8;
                uint32_t hi4[4], lo4[4];
#pragma unroll
                for (int p = 0; p < 4; p++) {
                    float v0 = hp[2 * p], v1 = hp[2 * p + 1];
                    __nv_bfloat16 h0b = __float2bfloat16(v0);
                    __nv_bfloat16 h1b = __float2bfloat16(v1);
                    __nv_bfloat162 hh;
                    hh.x = h0b;
                    hh.y = h1b;
                    hi4[p] = *(uint32_t*)&hh;
                    __nv_bfloat162 ll;
                    ll.x = __float2bfloat16(v0 - __bfloat162float(h0b));
                    ll.y = __float2bfloat16(v1 - __bfloat162float(h1b));
                    lo4[p] = *(uint32_t*)&ll;
                }
                uint32_t off = ((uint32_t)(row >> 3) + 16u) * 1024u +
                               (uint32_t)(row & 7) * 128u + (uint32_t)cg * 16u;
                uint32_t sw = swz128(off);
                *(uint4*)(smem + SM_AHI + sw) = make_uint4(hi4[0], hi4[1], hi4[2], hi4[3]);
                *(uint4*)(smem + SM_ALO + sw) = make_uint4(lo4[0], lo4[1], lo4[2], lo4[3]);
            }
        }
        TCGEN05_FENCE_BEFORE();
    }

    __syncthreads();
    if (wid == 0) TCGEN05_DEALLOC(tmem, 256);

    float* sP = (float*)(smem + SM_W);
    for (int idx = tid; idx < 4096; idx += 256) {
        int e = idx >> 6, h = idx & 63;
        sP[h * 65 + e] = w_l[(size_t)i * 4096 + idx];
    }
    __syncthreads();

    int bp = tid >> 1;
    int e0 = (tid & 1) * 32;
    float acc[32];
#pragma unroll
    for (int e = 0; e < 32; e++) acc[e] = b_l[i * 64 + e0 + e];
#pragma unroll 8
    for (int h = 0; h < 64; h++) {
        float hv = hbuf[bp * 65 + h];
#pragma unroll
        for (int e = 0; e < 32; e++) acc[e] = fmaf(sP[h * 65 + e0 + e], hv, acc[e]);
    }
    float* dst = d_feat + (size_t)(b0 + bp) * 448 + 64 + i * 64 + e0;
#pragma unroll
    for (int e = 0; e < 32; e++) dst[e] = tanhfast(acc[e]);
#endif  // HAS_TCGEN05
}

// ================= fp32 fallback LSTM =================
#define LSTM_SMEM_FLOATS (32768 + 2 * 8192 + 8192 + 256)
#define SXOFF 32768
#define SHOFF (32768 + 16384)
#define SBOFF (32768 + 16384 + 8192)

__device__ __forceinline__ void gemm_half(u64t acc[8][4], const float* __restrict__ vbase,
                                          const ulonglong2* __restrict__ sWp, int k0,
                                          int hc, int btb) {
#pragma unroll 4
    for (int kc = 0; kc < 32; kc++) {
        float2 vv[8];
#pragma unroll
        for (int bb = 0; bb < 8; bb++)
            vv[bb] = *(const float2*)(vbase + (btb + bb) * 64 + kc * 2);
#pragma unroll
        for (int kk = 0; kk < 2; kk++) {
            int k = k0 + kc * 2 + kk;
            ulonglong2 wlo = sWp[k * 64 + hc];
            ulonglong2 whi = sWp[k * 64 + 32 + hc];
#pragma unroll
            for (int bb = 0; bb < 8; bb++) {
                u64t vp = pk2(kk ? vv[bb].y : vv[bb].x);
                fma2(acc[bb][0], wlo.x, vp);
                fma2(acc[bb][1], wlo.y, vp);
                fma2(acc[bb][2], whi.x, vp);
                fma2(acc[bb][3], whi.y, vp);
            }
        }
    }
}

__global__ void __launch_bounds__(512, 1) lstm_fp32_kernel(const float* __restrict__ h0,
                                                           const float* __restrict__ c0,
                                                           const float* __restrict__ w_l,
                                                           const float* __restrict__ b_l) {
    if (d_useTC) return;
    extern __shared__ float sm[];
    float* sW = sm;
    float* sX = sm + SXOFF;
    float* sH = sm + SHOFF;
    float* sB = sm + SBOFF;
    int tid = threadIdx.x;
    int i = blockIdx.y;
    int b0 = blockIdx.x * 128;
    int hc = tid & 31;
    int btb = (tid >> 5) * 8;

    const float* wt = d_Wt + i * 32768;
#pragma unroll
    for (int j = 0; j < 16; j++) cpa16(sW + (tid + j * 512) * 4, wt + (tid + j * 512) * 4);
    {
        const float* mp = d_means + ((size_t)(5 * i + 0) * BATCH + b0) * 64;
        const float* hp = h0 + ((size_t)i * BATCH + b0) * 64;
#pragma unroll
        for (int j = 0; j < 4; j++) {
            int ch = tid + j * 512;
            cpa16(sX + ch * 4, mp + ch * 4);
            cpa16(sH + ch * 4, hp + ch * 4);
        }
    }
    asm volatile("cp.async.commit_group;");
    {
        const float* mp = d_means + ((size_t)(5 * i + 1) * BATCH + b0) * 64;
#pragma unroll
        for (int j = 0; j < 4; j++) {
            int ch = tid + j * 512;
            cpa16(sX + 8192 + ch * 4, mp + ch * 4);
        }
    }
    asm volatile("cp.async.commit_group;");

    if (tid < 256) sB[tid] = d_bias[i * 256 + tid];

    float cR[8][2];
#pragma unroll
    for (int bb = 0; bb < 8; bb++)
#pragma unroll
        for (int hp = 0; hp < 2; hp++)
            cR[bb][hp] = c0[((size_t)i * BATCH + b0 + btb + bb) * 64 + hc + hp * 32];

    const ulonglong2* sWp = (const ulonglong2*)sW;
    const ulonglong2* sBp = (const ulonglong2*)sB;

    for (int t = 0; t < 5; t++) {
        if (t < 4)
            asm volatile("cp.async.wait_group 1;");
        else
            asm volatile("cp.async.wait_group 0;");
        __syncthreads();

        u64t acc[8][4];
        {
            ulonglong2 bp0 = sBp[hc];
            ulonglong2 bp1 = sBp[32 + hc];
#pragma unroll
            for (int bb = 0; bb < 8; bb++) {
                acc[bb][0] = bp0.x;
                acc[bb][1] = bp0.y;
                acc[bb][2] = bp1.x;
                acc[bb][3] = bp1.y;
            }
        }
        gemm_half(acc, sX + (t & 1) * 8192, sWp, 0, hc, btb);
        gemm_half(acc, sH, sWp, 64, hc, btb);
        __syncthreads();

        if (t + 2 <= 4) {
            const float* mp = d_means + ((size_t)(5 * i + t + 2) * BATCH + b0) * 64;
#pragma unroll
            for (int j = 0; j < 4; j++) {
                int ch = tid + j * 512;
                cpa16(sX + (t & 1) * 8192 + ch * 4, mp + ch * 4);
            }
            asm volatile("cp.async.commit_group;");
        }

#pragma unroll
        for (int bb = 0; bb < 8; bb++) {
            int b = btb + bb;
#pragma unroll
            for (int hp = 0; hp < 2; hp++) {
                float gi, gf, gg, go;
                up2(acc[bb][hp * 2], gi, gf);
                up2(acc[bb][hp * 2 + 1], gg, go);
                float cc = sigf(gf) * cR[bb][hp] + sigf(gi) * tanhfast(gg);
                cR[bb][hp] = cc;
                sH[b * 64 + hc + hp * 32] = sigf(go) * tanhfast(cc);
            }
        }
    }
    __syncthreads();

    float* sP = sX;
    const float* wl = w_l + (size_t)i * 64 * 64;
    for (int idx = tid; idx < 4096; idx += 512) {
        int e = idx >> 6, h = idx & 63;
        sP[h * 65 + e] = wl[idx];
    }
    __syncthreads();

    float accp[8][2];
    {
        float bl0 = b_l[i * 64 + hc];
        float bl1 = b_l[i * 64 + 32 + hc];
#pragma unroll
        for (int bb = 0; bb < 8; bb++) {
            accp[bb][0] = bl0;
            accp[bb][1] = bl1;
        }
    }
#pragma unroll 8
    for (int h = 0; h < 64; h++) {
        float w0 = sP[h * 65 + hc];
        float w1 = sP[h * 65 + 32 + hc];
#pragma unroll
        for (int bb = 0; bb < 8; bb++) {
            float hv = sH[(btb + bb) * 64 + h];
            accp[bb][0] = fmaf(w0, hv, accp[bb][0]);
            accp[bb][1] = fmaf(w1, hv, accp[bb][1]);
        }
    }
#pragma unroll
    for (int bb = 0; bb < 8; bb++) {
        size_t base = (size_t)(b0 + btb + bb) * 448 + 64 + i * 64;
        d_feat[base + hc] = tanhfast(accp[bb][0]);
        d_feat[base + 32 + hc] = tanhfast(accp[bb][1]);
    }
}

// ---------------- final combine: bulk-copied weight stage (isolated test) ----------
#define FINAL_SMEM_BYTES (169216 + 16)
#define FIN_MBAR 169216

__global__ void __launch_bounds__(256) final_kernel(
    const float* __restrict__ x, const float* __restrict__ dw_b,
    float* __restrict__ out) {
    extern __shared__ __align__(16) float sm[];
    float* swide2 = sm;                          // 81*64 floats @ 0
    float* scq2 = sm + 81 * 64;                  // @ 20736 B
    float* scqu2 = sm + 81 * 64 + 448 * 64;      // @ 135424 B
    float* sb2 = scqu2 + 128 * 64;               // @ 168192 B
    int tid = threadIdx.x;
    uint32_t sbase = smem_u32(sm);
    if (tid == 0) {
        MBARRIER_INIT(sbase + FIN_MBAR, 1);
    }
    __syncthreads();
    if (tid == 0) {
        MBARRIER_EXPECT_TX(sbase + FIN_MBAR, 169216u);
        cpbulk(sbase + 0, d_wideT, 20736u, sbase + FIN_MBAR);
        cpbulk(sbase + 20736, d_cqT, 114688u, sbase + FIN_MBAR);
        cpbulk(sbase + 135424, d_cquT, 32768u, sbase + FIN_MBAR);
        cpbulk(sbase + 168192, d_headB, 1024u, sbase + FIN_MBAR);
    }
    MBARRIER_WAIT_PARITY(sbase + FIN_MBAR, 0);
    __syncthreads();

    const u64t* swide2u = (const u64t*)swide2;
    const u64t* scq2u = (const u64t*)scq2;
    const u64t* scqu2u = (const u64t*)scqu2;
    const u64t* sb2u = (const u64t*)sb2;

    int warp = tid >> 5, lane = tid & 31;
    float dwb0 = __ldg(dw_b);
    int bstart = blockIdx.x * 32 + warp * 4;

    u64t aw[4];
    {
        u64t bw = sb2u[lane];
#pragma unroll
        for (int t = 0; t < 4; t++) aw[t] = bw;
    }
#pragma unroll 3
    for (int j = 0; j < 81; j++) {
        float4 xv = __ldg((const float4*)(x + (size_t)j * BATCH + bstart));
        u64t w2 = swide2u[j * 32 + lane];
        fma2(aw[0], w2, pk2(xv.x));
        fma2(aw[1], w2, pk2(xv.y));
        fma2(aw[2], w2, pk2(xv.z));
        fma2(aw[3], w2, pk2(xv.w));
    }
    float w0[4], w1[4];
#pragma unroll
    for (int t = 0; t < 4; t++) {
        float a, b;
        up2(aw[t], a, b);
        w0[t] = tanhfast(a);
        w1[t] = tanhfast(b);
    }

    u64t aq[4];
    {
        u64t bq = sb2u[32 + lane];
#pragma unroll
        for (int t = 0; t < 4; t++) aq[t] = bq;
    }
#pragma unroll 2
    for (int j4 = 0; j4 < 112; j4++) {
        float f0[4], f1[4], f2[4], f3[4];
        *(float4*)f0 = ((const float4*)(d_feat + (size_t)(bstart + 0) * 448))[j4];
        *(float4*)f1 = ((const float4*)(d_feat + (size_t)(bstart + 1) * 448))[j4];
        *(float4*)f2 = ((const float4*)(d_feat + (size_t)(bstart + 2) * 448))[j4];
        *(float4*)f3 = ((const float4*)(d_feat + (size_t)(bstart + 3) * 448))[j4];
#pragma unroll
        for (int jj = 0; jj < 4; jj++) {
            u64t w2 = scq2u[(j4 * 4 + jj) * 32 + lane];
            fma2(aq[0], w2, pk2(f0[jj]));
            fma2(aq[1], w2, pk2(f1[jj]));
            fma2(aq[2], w2, pk2(f2[jj]));
            fma2(aq[3], w2, pk2(f3[jj]));
        }
    }
    float q0[4], q1[4];
#pragma unroll
    for (int t = 0; t < 4; t++) {
        float a, b;
        up2(aq[t], a, b);
        q0[t] = tanhfast(a);
        q1[t] = tanhfast(b);
    }

#pragma unroll
    for (int t = 0; t < 4; t++) {
        u64t a = sb2u[64 + lane];
#pragma unroll
        for (int j = 0; j < 32; j++) {
            float v = __shfl_sync(0xffffffffu, q0[t], j);
            fma2(a, scqu2u[j * 32 + lane], pk2(v));
        }
#pragma unroll
        for (int j = 0; j < 32; j++) {
            float v = __shfl_sync(0xffffffffu, q1[t], j);
            fma2(a, scqu2u[(32 + j) * 32 + lane], pk2(v));
        }
#pragma unroll
        for (int j = 0; j < 32; j++) {
            float v = __shfl_sync(0xffffffffu, w0[t], j);
            fma2(a, scqu2u[(64 + j) * 32 + lane], pk2(v));
        }
#pragma unroll
        for (int j = 0; j < 32; j++) {
            float v = __shfl_sync(0xffffffffu, w1[t], j);
            fma2(a, scqu2u[(96 + j) * 32 + lane], pk2(v));
        }
        float x0, x1;
        up2(a, x0, x1);
        float qw0 = tanhfast(x0), qw1 = tanhfast(x1);
        float d0, d1;
        up2(sb2u[96 + lane], d0, d1);
        float r = d0 * qw0 + d1 * qw1;
#pragma unroll
        for (int off = 16; off; off >>= 1) r += __shfl_xor_sync(0xffffffffu, r, off);
        if (lane == 0) out[bstart + t] = r + dwb0;
    }
}

// ---------------- launch ----------------
extern "C" void kernel_launch(void* const* d_in, const int* in_sizes, int n_in,
                              void* d_out, int out_size) {
    const float* x = (const float*)d_in[0];
    const float* emb = (const float*)d_in[1];
    const float* Wih = (const float*)d_in[2];
    const float* Whh = (const float*)d_in[3];
    const float* bih = (const float*)d_in[4];
    const float* bhh = (const float*)d_in[5];
    const float* h0 = (const float*)d_in[6];
    const float* c0 = (const float*)d_in[7];
    const float* w_l = (const float*)d_in[8];
    const float* b_l = (const float*)d_in[9];
    const float* conv1_w = (const float*)d_in[10];
    const float* conv1_b = (const float*)d_in[11];
    const float* lin1_w = (const float*)d_in[12];
    const float* lin1_b = (const float*)d_in[13];
    const float* conv2_w = (const float*)d_in[14];
    const float* conv2_b = (const float*)d_in[15];
    const float* lin2_w = (const float*)d_in[16];
    const float* lin2_b = (const float*)d_in[17];
    const float* wide_w = (const float*)d_in[18];
    const float* wide_b = (const float*)d_in[19];
    const float* cq_w = (const float*)d_in[20];
    const float* cq_b = (const float*)d_in[21];
    const float* cqu_w = (const float*)d_in[22];
    const float* cqu_b = (const float*)d_in[23];
    const float* dw_w = (const float*)d_in[24];
    const float* dw_b = (const float*)d_in[25];
    float* out = (float*)d_out;

    prep_kernel<<<760, 256>>>(Wih, Whh, bih, bhh, wide_w, wide_b, cq_w, cq_b,
                              cqu_w, cqu_b, dw_w, x);
    mean_kernel<<<(31 * 2048) / 8, 256>>>(x, emb);

    cudaFuncSetAttribute(lstm_fp32_kernel, cudaFuncAttributeMaxDynamicSharedMemorySize,
                         LSTM_SMEM_FLOATS * 4);
    lstm_fp32_kernel<<<dim3(32, 4), 512, LSTM_SMEM_FLOATS * 4>>>(h0, c0, w_l, b_l);

    cudaFuncSetAttribute(lstm_tc_kernel, cudaFuncAttributeMaxDynamicSharedMemorySize,
                         TC_SMEM_BYTES);
    lstm_tc_kernel<<<148, 256, TC_SMEM_BYTES>>>(h0, c0, w_l, b_l,
                                                conv1_w, conv1_b, lin1_w, lin1_b,
                                                conv2_w, conv2_b, lin2_w, lin2_b);

    cudaFuncSetAttribute(final_kernel, cudaFuncAttributeMaxDynamicSharedMemorySize,
                         FINAL_SMEM_BYTES);
    final_kernel<<<128, 256, FINAL_SMEM_BYTES>>>(x, dw_b, out);
}

// round 17
// speedup vs baseline: 1.1026x; 1.0121x over previous
#include <cuda_runtime.h>
#include <cuda_bf16.h>
#include <math.h>
#include <cstdint>

#define BATCH 4096

#if defined(__CUDA_ARCH_FEAT_SM103_ALL) || defined(__CUDA_ARCH_FEAT_SM100_ALL)
#define HAS_TCGEN05 1
#else
#define HAS_TCGEN05 0
#endif

// ---------------- scratch (device globals; no allocation allowed) ----------------
__device__ int d_useTC;
__device__ int d_cntp[31 * 8];
__device__ __align__(256) float d_means[30 * BATCH * 64];
__device__ __align__(256) float d_feat[BATCH * 448];
__device__ __align__(256) float d_Wt[4 * 128 * 256];          // fp32 path
__device__ float d_bias[4 * 256];                             // fp32 path
__device__ __align__(256) __nv_bfloat16 d_Whi[4 * 2 * 16384]; // tc path
__device__ __align__(256) __nv_bfloat16 d_Wlo[4 * 2 * 16384];
__device__ float d_biasI[4 * 256];
__device__ __align__(256) __nv_bfloat16 d_xhi[20 * 32 * 8192];
__device__ __align__(256) __nv_bfloat16 d_xlo[20 * 32 * 8192];
__device__ __align__(256) float2 d_wideT[81 * 32];
__device__ __align__(256) float2 d_cqT[448 * 32];
__device__ __align__(256) float2 d_cquT[128 * 32];
__device__ __align__(256) float2 d_headB[4 * 32];

__constant__ int c_gstart[31] = {
    276,
    211, 224, 237, 250, 263,
    662, 672, 682, 692, 702,
    612, 622, 632, 642, 652,
    397, 410, 423, 436, 449,
    512, 522, 532, 542, 552,
    862, 872, 882, 892, 902};
__constant__ int c_grows[31] = {
    10,
    10, 10, 10, 10, 10,
    5, 5, 5, 5, 5,
    5, 5, 5, 5, 5,
    10, 10, 10, 10, 10,
    5, 5, 5, 5, 5,
    5, 5, 5, 5, 5};

__device__ __forceinline__ float sigf(float x) { return 1.0f / (1.0f + __expf(-x)); }
__device__ __forceinline__ float tanhfast(float x) {
    return fmaf(2.0f, 1.0f / (1.0f + __expf(-2.0f * x)), -1.0f);
}
__device__ __forceinline__ float tanha(float x) {
    float y;
    asm("tanh.approx.f32 %0, %1;" : "=f"(y) : "f"(x));
    return y;
}
__device__ __forceinline__ float siga(float x) {
    return fmaf(0.5f, tanha(0.5f * x), 0.5f);
}
__device__ __forceinline__ void cpa16(void* dst, const void* src) {
    unsigned a = (unsigned)__cvta_generic_to_shared(dst);
    asm volatile("cp.async.cg.shared.global [%0], [%1], 16;" ::"r"(a), "l"(src));
}
__device__ __forceinline__ uint32_t smem_u32(const void* p) {
    return (uint32_t)__cvta_generic_to_shared(p);
}
static __device__ __forceinline__ uint32_t swz128(uint32_t off) {
    return off ^ ((off >> 3) & 0x70);
}
typedef unsigned long long u64t;
__device__ __forceinline__ void fma2(u64t& d, u64t a, u64t b) {
    asm("fma.rn.f32x2 %0, %1, %2, %0;" : "+l"(d) : "l"(a), "l"(b));
}
__device__ __forceinline__ u64t pk2(float v) {
    u64t r;
    asm("mov.b64 %0, {%1, %1};" : "=l"(r) : "f"(v));
    return r;
}
__device__ __forceinline__ void up2(u64t v, float& lo, float& hi) {
    asm("mov.b64 {%0, %1}, %2;" : "=f"(lo), "=f"(hi) : "l"(v));
}
__device__ __forceinline__ uint32_t bf2pack(float a, float b) {
    __nv_bfloat162 h;
    h.x = __float2bfloat16(a);
    h.y = __float2bfloat16(b);
    return *(uint32_t*)&h;
}

// -------- bulk-copy + mbarrier (final_kernel only; crashes alongside tcgen05) --------
__device__ __forceinline__ void cpbulk(uint32_t dst_smem, const void* src,
                                       uint32_t bytes, uint32_t mbar) {
    asm volatile(
        "cp.async.bulk.shared::cta.global.mbarrier::complete_tx::bytes [%0], [%1], %2, [%3];"
        :: "r"(dst_smem), "l"(src), "r"(bytes), "r"(mbar)
        : "memory");
}
#define MBARRIER_INIT(mb, n) \
    asm volatile("mbarrier.init.shared.b64 [%0], %1;" ::"r"(mb), "r"(n) : "memory")
#define MBARRIER_EXPECT_TX(mb, bytes) \
    asm volatile("mbarrier.arrive.expect_tx.shared.b64 _, [%0], %1;" ::"r"(mb), "r"(bytes) : "memory")
#define MBARRIER_WAIT_PARITY(mb, ph) do { \
    uint32_t _mb = (mb), _p = (ph), _done; \
    asm volatile("{\n\t.reg .pred p;\n\tmbarrier.try_wait.parity.acquire.cta.shared::cta.b64 p, [%1], %2;\n\tselp.b32 %0, 1, 0, p;\n\t}" \
        : "=r"(_done) : "r"(_mb), "r"(_p) : "memory"); \
    if (!_done) { \
        asm volatile("{\n\t.reg .pred P1;\n\tWL_%=:\n\tmbarrier.try_wait.parity.acquire.cta.shared::cta.b64 P1, [%0], %1, 0x989680;\n\t@P1 bra.uni WD_%=;\n\tbra.uni WL_%=;\n\tWD_%=:\n\t}" \
            :: "r"(_mb), "r"(_p) : "memory"); \
    } \
} while (0)

// ---------------- prep + count fused ----------------
__global__ void prep_kernel(const float* __restrict__ Wih, const float* __restrict__ Whh,
                            const float* __restrict__ bih, const float* __restrict__ bhh,
                            const float* __restrict__ wide_w, const float* __restrict__ wide_b,
                            const float* __restrict__ cq_w, const float* __restrict__ cq_b,
                            const float* __restrict__ cqu_w, const float* __restrict__ cqu_b,
                            const float* __restrict__ dw_w, const float* __restrict__ x) {
    if (blockIdx.x >= 512) {
        int cb = blockIdx.x - 512;
        int g = cb >> 3;
        int part = cb & 7;
        int n = c_grows[g] * BATCH;
        const float* p = x + (size_t)c_gstart[g] * BATCH;
        int cnt = 0;
        for (int i = part * 256 + threadIdx.x; i < n; i += 2048) cnt += (p[i] != 0.0f);
#pragma unroll
        for (int o = 16; o; o >>= 1) cnt += __shfl_xor_sync(0xffffffffu, cnt, o);
        __shared__ int wsum[8];
        if ((threadIdx.x & 31) == 0) wsum[threadIdx.x >> 5] = cnt;
        __syncthreads();
        if (threadIdx.x == 0) {
            int s = 0;
#pragma unroll
            for (int w = 0; w < 8; w++) s += wsum[w];
            d_cntp[g * 8 + part] = s;
        }
        return;
    }
    int idx = blockIdx.x * 256 + threadIdx.x;  // 131072 total
    if (idx == 0) d_useTC = HAS_TCGEN05;
#if !HAS_TCGEN05
    {
        int c = idx & 255;
        int k = (idx >> 8) & 127;
        int i = idx >> 15;
        int h = ((c & 127) >> 2) + ((c >> 7) << 5);
        int t = c & 3;
        int g = t * 64 + h;
        float v = (k < 64) ? Wih[(i * 256 + g) * 64 + k]
                           : Whh[(i * 256 + g) * 64 + (k - 64)];
        d_Wt[idx] = v;
    }
    if (idx < 1024) {
        int i = idx >> 8;
        int c = idx & 255;
        int h = ((c & 127) >> 2) + ((c >> 7) << 5);
        int t = c & 3;
        int g = i * 256 + t * 64 + h;
        d_bias[idx] = bih[g] + bhh[g];
    }
#else
    {
        int i = idx >> 15;
        int rem = idx & 32767;
        int gb = rem >> 14;
        int rem2 = rem & 16383;
        int n = rem2 >> 7;
        int k = rem2 & 127;
        int t = n & 3;
        int hib = n >> 2;
        int g = t * 64 + 32 * gb + hib;
        float v = (k < 64) ? Wih[(i * 256 + g) * 64 + k]
                           : Whh[(i * 256 + g) * 64 + (k - 64)];
        __nv_bfloat16 hi = __float2bfloat16(v);
        __nv_bfloat16 lo = __float2bfloat16(v - __bfloat162float(hi));
        uint32_t off = ((uint32_t)(n >> 3) + ((uint32_t)(k >> 6) << 4)) * 1024u +
                       (uint32_t)(n & 7) * 128u + (uint32_t)(k & 63) * 2u;
        uint32_t sw = swz128(off) >> 1;
        int tile = i * 2 + gb;
        d_Whi[tile * 16384 + sw] = hi;
        d_Wlo[tile * 16384 + sw] = lo;
    }
    if (idx < 1024) {
        int i = idx >> 8;
        int c = idx & 255;
        int gb = c >> 7;
        int hib = (c & 127) >> 2;
        int t = c & 3;
        int src = i * 256 + t * 64 + 32 * gb + hib;
        d_biasI[idx] = bih[src] + bhh[src];
    }
#endif
    if (idx < 14336) {
        int j = idx >> 5, o = idx & 31;
        d_cqT[idx] = make_float2(cq_w[o * 448 + j], cq_w[(o + 32) * 448 + j]);
    }
    if (idx < 4096) {
        int j = idx >> 5, o = idx & 31;
        d_cquT[idx] = make_float2(cqu_w[o * 128 + j], cqu_w[(o + 32) * 128 + j]);
    }
    if (idx < 2592) {
        int j = idx >> 5, o = idx & 31;
        d_wideT[idx] = make_float2(wide_w[o * 81 + j], wide_w[(o + 32) * 81 + j]);
    }
    if (idx < 32) {
        d_headB[idx] = make_float2(wide_b[idx], wide_b[idx + 32]);
        d_headB[32 + idx] = make_float2(cq_b[idx], cq_b[idx + 32]);
        d_headB[64 + idx] = make_float2(cqu_b[idx], cqu_b[idx + 32]);
        d_headB[96 + idx] = make_float2(dw_w[idx], dw_w[idx + 32]);
    }
}

// ---------------- gathers + means ----------------
__global__ void mean_kernel(const float* __restrict__ x, const float* __restrict__ emb) {
    int w = blockIdx.x * 8 + (threadIdx.x >> 5);
    int lane = threadIdx.x & 31;
    int half = lane >> 4;
    int li = lane & 15;
    int g = w >> 11;
    int bp = w & 2047;
    int b = bp * 2 + half;

    int cpart = (lane < 8) ? d_cntp[g * 8 + lane] : 0;
#pragma unroll
    for (int o = 4; o; o >>= 1) cpart += __shfl_xor_sync(0xffffffffu, cpart, o);
    cpart = __shfl_sync(0xffffffffu, cpart, 0);
    float L = fminf(fmaxf((float)cpart, 1.0f), (float)c_grows[g]);
    int Lu = (int)(L + 0.5f);

    const float* xcol = x + (size_t)c_gstart[g] * BATCH + b;
    int tokr = 0;
    if (li < Lu) tokr = (int)xcol[(size_t)li * BATCH];

    float a0 = 0.0f, a1 = 0.0f, a2 = 0.0f, a3 = 0.0f;
    const float4* emb4 = (const float4*)emb;
#pragma unroll
    for (int r = 0; r < 10; r++) {
        if (r < Lu) {
            int tok = __shfl_sync(0xffffffffu, tokr, (lane & 16) + r);
            float4 v = __ldg(emb4 + (size_t)tok * 16 + li);
            a0 += v.x;
            a1 += v.y;
            a2 += v.z;
            a3 += v.w;
        }
    }
    float inv = 1.0f / L;
    a0 *= inv; a1 *= inv; a2 *= inv; a3 *= inv;

    if (g == 0) {
        ((float4*)(d_feat + (size_t)b * 448))[li] = make_float4(a0, a1, a2, a3);
    } else if (g <= 20 && d_useTC) {
        int row = b & 127;
        int tile = b >> 7;
        uint32_t off = (uint32_t)(row >> 3) * 1024u + (uint32_t)(row & 7) * 128u +
                       (uint32_t)li * 8u;
        uint32_t sw = swz128(off);
        uint32_t hi01 = bf2pack(a0, a1);
        uint32_t hi23 = bf2pack(a2, a3);
        __nv_bfloat16 h0 = __float2bfloat16(a0), h1 = __float2bfloat16(a1);
        __nv_bfloat16 h2 = __float2bfloat16(a2), h3 = __float2bfloat16(a3);
        uint32_t lo01 = bf2pack(a0 - __bfloat162float(h0), a1 - __bfloat162float(h1));
        uint32_t lo23 = bf2pack(a2 - __bfloat162float(h2), a3 - __bfloat162float(h3));
        size_t base = ((size_t)(g - 1) * 32 + tile) * 8192;
        *(u64t*)((char*)(d_xhi + base) + sw) = (u64t)hi01 | ((u64t)hi23 << 32);
        *(u64t*)((char*)(d_xlo + base) + sw) = (u64t)lo01 | ((u64t)lo23 << 32);
    } else {
        ((float4*)(d_means + ((size_t)(g - 1) * BATCH + b) * 64))[li] =
            make_float4(a0, a1, a2, a3);
    }
}

// ================= fused LSTM(tc) + CNN kernel (proven cp.async staging) ==========
#define SM_AHI 0
#define SM_ALO 32768
#define SM_W 65536
#define SM_BIAS 196608
#define SM_PTR 197632
#define SM_MBAR0 197640
#define SM_MBAR1 197648
#define SM_HBUF 197664          // 128*65 floats
#define TC_SMEM_BYTES (197664 + 33280)

#if HAS_TCGEN05
static constexpr uint64_t SMEM_DESC_BASE_SW128 =
    (uint64_t(2) << 61) | (uint64_t(1) << 46) | (uint64_t(64) << 32) | (uint64_t(1) << 16);
#define MAKE_SMEM_DESC(base_addr) \
    (SMEM_DESC_BASE_SW128 | ((uint64_t)((base_addr) >> 4) & 0x3FFF))
#define LSTM_IDESC 0x8200490u

__device__ __forceinline__ uint32_t elect_one_pred() {
    uint32_t pred;
    asm volatile(
        "{\n\t.reg .pred p;\n\telect.sync _|p, 0xFFFFFFFF;\n\tselp.b32 %0, 1, 0, p;\n\t}"
        : "=r"(pred));
    return pred;
}
__device__ __forceinline__ void mma_f16_ss(uint32_t d, uint64_t a, uint64_t b,
                                           uint32_t idesc, bool accum) {
    uint32_t en = accum ? 1u : 0u;
    asm volatile(
        "{\n\t"
        ".reg .pred p;\n\t"
        "setp.ne.u32 p, %4, 0;\n\t"
        "tcgen05.mma.cta_group::1.kind::f16 [%0], %1, %2, %3, {%5, %5, %5, %5}, p;\n\t"
        "}"
        :: "r"(d), "l"(a), "l"(b), "r"(idesc), "r"(en), "r"(0u)
        : "memory");
}
#define TCGEN05_ALLOC(sa, n) \
    asm volatile("tcgen05.alloc.cta_group::1.sync.aligned.shared::cta.b32 [%0], %1;" ::"r"(sa), "r"(n) : "memory")
#define TCGEN05_DEALLOC(t, n) \
    asm volatile("tcgen05.dealloc.cta_group::1.sync.aligned.b32 %0, %1;" ::"r"(t), "r"(n))
#define TCGEN05_RELINQ() \
    asm volatile("tcgen05.relinquish_alloc_permit.cta_group::1.sync.aligned;")
#define TCGEN05_COMMIT(mb) \
    asm volatile("tcgen05.commit.cta_group::1.mbarrier::arrive::one.shared::cluster.b64 [%0];" ::"r"(mb) : "memory")
#define TCGEN05_FENCE_BEFORE() asm volatile("tcgen05.fence::before_thread_sync;" ::: "memory")
#define TCGEN05_FENCE_AFTER() asm volatile("tcgen05.fence::after_thread_sync;" ::: "memory")
#define TCGEN05_WAIT_LD() asm volatile("tcgen05.wait::ld.sync.aligned;" ::: "memory")
#define FENCE_PROXY_ASYNC() asm volatile("fence.proxy.async.shared::cta;" ::: "memory")
#define LDTM_X32(r, addr) \
    asm volatile( \
        "tcgen05.ld.sync.aligned.32x32b.x32.b32 " \
        "{%0, %1, %2, %3, %4, %5, %6, %7, %8, %9, %10, %11, %12, %13, %14, %15, " \
        " %16, %17, %18, %19, %20, %21, %22, %23, %24, %25, %26, %27, %28, %29, %30, %31}, [%32];" \
        : "=r"((r)[0]), "=r"((r)[1]), "=r"((r)[2]), "=r"((r)[3]), "=r"((r)[4]), "=r"((r)[5]), \
          "=r"((r)[6]), "=r"((r)[7]), "=r"((r)[8]), "=r"((r)[9]), "=r"((r)[10]), "=r"((r)[11]), \
          "=r"((r)[12]), "=r"((r)[13]), "=r"((r)[14]), "=r"((r)[15]), "=r"((r)[16]), "=r"((r)[17]), \
          "=r"((r)[18]), "=r"((r)[19]), "=r"((r)[20]), "=r"((r)[21]), "=r"((r)[22]), "=r"((r)[23]), \
          "=r"((r)[24]), "=r"((r)[25]), "=r"((r)[26]), "=r"((r)[27]), "=r"((r)[28]), "=r"((r)[29]), \
          "=r"((r)[30]), "=r"((r)[31]) \
        : "r"(addr))
#endif  // HAS_TCGEN05

// cnn work for one (s, b) item
__device__ __forceinline__ void cnn_item(const float* scw, const float* slw,
                                         const float* scb, const float* slb,
                                         int s, int b) {
    float y[12][4];
#pragma unroll
    for (int o = 0; o < 12; o++)
#pragma unroll
        for (int tt = 0; tt < 4; tt++) y[o][tt] = scb[s * 12 + o];

    const float* cwp = scw + s * 1536;
    int gbase = 20 + s * 5;
    for (int e4 = 0; e4 < 16; e4++) {
        float mv[5][4];
#pragma unroll
        for (int t = 0; t < 5; t++) {
            float4 m4 = *(const float4*)(d_means + ((size_t)(gbase + t) * BATCH + b) * 64 + e4 * 4);
            mv[t][0] = m4.x; mv[t][1] = m4.y; mv[t][2] = m4.z; mv[t][3] = m4.w;
        }
#pragma unroll
        for (int ee = 0; ee < 4; ee++) {
            int e = e4 * 4 + ee;
#pragma unroll
            for (int o = 0; o < 12; o++) {
                float w0 = cwp[o * 128 + e];
                float w1 = cwp[o * 128 + 64 + e];
#pragma unroll
                for (int tt = 0; tt < 4; tt++)
                    y[o][tt] = fmaf(mv[tt][ee], w0, fmaf(mv[tt + 1][ee], w1, y[o][tt]));
            }
        }
    }
    float p[24];
#pragma unroll
    for (int o = 0; o < 12; o++) {
#pragma unroll
        for (int j = 0; j < 2; j++)
            p[j * 12 + o] = fmaxf(fmaxf(y[o][2 * j], y[o][2 * j + 1]), 0.0f);
    }
    const float* lwp = slw + s * 1536;
    float* dst = d_feat + (size_t)b * 448 + 320 + s * 64;
    for (int eo = 0; eo < 64; eo++) {
        float acc = slb[s * 64 + eo];
#pragma unroll
        for (int j = 0; j < 24; j++) acc = fmaf(lwp[eo * 24 + j], p[j], acc);
        dst[eo] = fmaxf(acc, 0.0f);
    }
}

__global__ void __launch_bounds__(256, 1) lstm_tc_kernel(
    const float* __restrict__ h0, const float* __restrict__ c0,
    const float* __restrict__ w_l, const float* __restrict__ b_l,
    const float* __restrict__ cw1, const float* __restrict__ cb1,
    const float* __restrict__ lw1, const float* __restrict__ lb1,
    const float* __restrict__ cw2, const float* __restrict__ cb2,
    const float* __restrict__ lw2, const float* __restrict__ lb2) {
    extern __shared__ __align__(1024) char smem[];
    int tid = threadIdx.x;

    if (blockIdx.x >= 128) {
        // ---- CNN blocks (both arch paths) ----
        float* scw = (float*)smem;
        float* slw = scw + 3072;
        float* scb = slw + 3072;
        float* slb = scb + 32;
        for (int idx = tid; idx < 1536; idx += 256) {
            scw[idx] = cw1[idx];
            scw[1536 + idx] = cw2[idx];
            slw[idx] = lw1[idx];
            slw[1536 + idx] = lw2[idx];
        }
        if (tid < 12) {
            scb[tid] = cb1[tid];
            scb[12 + tid] = cb2[tid];
        }
        if (tid < 64) {
            slb[tid] = lb1[tid];
            slb[64 + tid] = lb2[tid];
        }
        __syncthreads();
        for (int item = (blockIdx.x - 128) * 256 + tid; item < 8192; item += 5120) {
            int s = item >> 12;
            int b = item & 4095;
            cnn_item(scw, slw, scb, slb, s, b);
        }
        return;
    }

#if HAS_TCGEN05
    uint32_t sbase = smem_u32(smem);
    int wid = tid >> 5;
    int lane = tid & 31;
    int i = blockIdx.x >> 5;
    int bx = blockIdx.x & 31;
    int b0 = bx * 128;

    if (wid == 0) {
        TCGEN05_ALLOC(sbase + SM_PTR, 256);
    } else {
        TCGEN05_RELINQ();
    }

    {
        const char* whi = (const char*)(d_Whi + (size_t)i * 2 * 16384);
        const char* wlo = (const char*)(d_Wlo + (size_t)i * 2 * 16384);
#pragma unroll
        for (int j = 0; j < 16; j++) {
            int ch = (tid + j * 256) * 16;
            cpa16(smem + SM_W + ch, whi + ch);
            cpa16(smem + SM_W + 65536 + ch, wlo + ch);
        }
        size_t xb = ((size_t)(i * 5) * 32 + bx) * 8192;
        const char* xh = (const char*)(d_xhi + xb);
        const char* xl = (const char*)(d_xlo + xb);
#pragma unroll
        for (int j = 0; j < 4; j++) {
            int ch = (tid + j * 256) * 16;
            cpa16(smem + SM_AHI + ch, xh + ch);
            cpa16(smem + SM_ALO + ch, xl + ch);
        }
    }
    asm volatile("cp.async.commit_group;");

    __syncthreads();
    uint32_t tmem;
    asm volatile("ld.shared.b32 %0, [%1];" : "=r"(tmem) : "r"(sbase + SM_PTR));

    for (int idx = tid; idx < 8192; idx += 256) {
        int row = idx >> 6, col = idx & 63;
        float v = h0[((size_t)(i << 12) + b0 + row) * 64 + col];
        __nv_bfloat16 hi = __float2bfloat16(v);
        __nv_bfloat16 lo = __float2bfloat16(v - __bfloat162float(hi));
        uint32_t off = ((uint32_t)(row >> 3) + 16u) * 1024u + (uint32_t)(row & 7) * 128u +
                       (uint32_t)col * 2u;
        uint32_t sw = swz128(off);
        *(__nv_bfloat16*)(smem + SM_AHI + sw) = hi;
        *(__nv_bfloat16*)(smem + SM_ALO + sw) = lo;
    }
    float* sBias = (float*)(smem + SM_BIAS);
    sBias[tid] = d_biasI[i * 256 + tid];

    int gb = wid >> 2;
    int bloc = ((wid & 3) << 5) + lane;
    uint32_t mymbar = sbase + (gb ? SM_MBAR1 : SM_MBAR0);

    float cR[32];
    {
        const float4* cp4 =
            (const float4*)(c0 + ((size_t)(i << 12) + b0 + bloc) * 64 + (gb << 5));
#pragma unroll
        for (int q = 0; q < 8; q++) {
            float4 v = cp4[q];
            cR[q * 4 + 0] = v.x;
            cR[q * 4 + 1] = v.y;
            cR[q * 4 + 2] = v.z;
            cR[q * 4 + 3] = v.w;
        }
    }

    if (tid == 0) {
        MBARRIER_INIT(sbase + SM_MBAR0, 1);
        MBARRIER_INIT(sbase + SM_MBAR1, 1);
    }
    __syncthreads();

    float* hbuf = (float*)(smem + SM_HBUF);

    for (int t = 0; t < 5; t++) {
        asm volatile("cp.async.wait_group 0;");
        __syncthreads();
        FENCE_PROXY_ASYNC();

        if (wid == 0) {
            TCGEN05_FENCE_AFTER();
            if (elect_one_pred()) {
                uint64_t ahi = MAKE_SMEM_DESC(sbase + SM_AHI);
                uint64_t alo = MAKE_SMEM_DESC(sbase + SM_ALO);
#pragma unroll
                for (int g2 = 0; g2 < 2; g2++) {
                    uint64_t bhi = MAKE_SMEM_DESC(sbase + SM_W + g2 * 32768);
                    uint64_t blo = MAKE_SMEM_DESC(sbase + SM_W + 65536 + g2 * 32768);
                    uint32_t dd = tmem + g2 * 128;
#pragma unroll
                    for (int s = 0; s < 8; s++) {
                        uint64_t ko = (s < 4) ? (uint64_t)(2 * s) : (uint64_t)(1024 + 2 * (s - 4));
                        mma_f16_ss(dd, ahi + ko, bhi + ko, LSTM_IDESC, s > 0);
                    }
#pragma unroll
                    for (int s = 0; s < 8; s++) {
                        uint64_t ko = (s < 4) ? (uint64_t)(2 * s) : (uint64_t)(1024 + 2 * (s - 4));
                        mma_f16_ss(dd, alo + ko, bhi + ko, LSTM_IDESC, true);
                    }
#pragma unroll
                    for (int s = 0; s < 8; s++) {
                        uint64_t ko = (s < 4) ? (uint64_t)(2 * s) : (uint64_t)(1024 + 2 * (s - 4));
                        mma_f16_ss(dd, ahi + ko, blo + ko, LSTM_IDESC, true);
                    }
                    TCGEN05_COMMIT(sbase + (g2 ? SM_MBAR1 : SM_MBAR0));
                }
            }
        }
        MBARRIER_WAIT_PARITY(mymbar, t & 1);
        TCGEN05_FENCE_AFTER();

        // epilogue: gates -> c,h ; h to conflict-free fp32 hbuf
#pragma unroll
        for (int chunk = 0; chunk < 4; chunk++) {
            uint32_t r[32];
            LDTM_X32(r, tmem + gb * 128 + chunk * 32);
            TCGEN05_WAIT_LD();
#pragma unroll
            for (int jj = 0; jj < 8; jj++) {
                int hib = chunk * 8 + jj;
                int cb = gb * 128 + chunk * 32 + jj * 4;
                float gi = __uint_as_float(r[jj * 4 + 0]) + sBias[cb + 0];
                float gf = __uint_as_float(r[jj * 4 + 1]) + sBias[cb + 1];
                float gg = __uint_as_float(r[jj * 4 + 2]) + sBias[cb + 2];
                float go = __uint_as_float(r[jj * 4 + 3]) + sBias[cb + 3];
                float cc = siga(gf) * cR[hib] + siga(gi) * tanha(gg);
                cR[hib] = cc;
                float hv = siga(go) * tanha(cc);
                hbuf[bloc * 65 + (gb << 5) + hib] = hv;
            }
        }
        __syncthreads();  // hbuf complete AND both mma mbars fired -> all MMAs done

        if (t < 4) {
            // prefetch x(t+1) via cp.async (safe: all MMAs done reading atom-col 0)
            size_t xb = ((size_t)(i * 5 + t + 1) * 32 + bx) * 8192;
            const char* xh = (const char*)(d_xhi + xb);
            const char* xl = (const char*)(d_xlo + xb);
#pragma unroll
            for (int j = 0; j < 4; j++) {
                int ch = (tid + j * 256) * 16;
                cpa16(smem + SM_AHI + ch, xh + ch);
                cpa16(smem + SM_ALO + ch, xl + ch);
            }
            asm volatile("cp.async.commit_group;");

            // reshape: hbuf -> swizzled bf16 hi/lo h atoms (STS.128, conflict-free)
#pragma unroll
            for (int u = 0; u < 4; u++) {
                int unit = tid + u * 256;
                int row = unit >> 3, cg = unit & 7;
                const float* hp = hbuf + row * 65 + cg * 8;
                uint32_t hi4[4], lo4[4];
#pragma unroll
                for (int p = 0; p < 4; p++) {
                    float v0 = hp[2 * p], v1 = hp[2 * p + 1];
                    __nv_bfloat16 h0b = __float2bfloat16(v0);
                    __nv_bfloat16 h1b = __float2bfloat16(v1);
                    __nv_bfloat162 hh;
                    hh.x = h0b;
                    hh.y = h1b;
                    hi4[p] = *(uint32_t*)&hh;
                    __nv_bfloat162 ll;
                    ll.x = __float2bfloat16(v0 - __bfloat162float(h0b));
                    ll.y = __float2bfloat16(v1 - __bfloat162float(h1b));
                    lo4[p] = *(uint32_t*)&ll;
                }
                uint32_t off = ((uint32_t)(row >> 3) + 16u) * 1024u +
                               (uint32_t)(row & 7) * 128u + (uint32_t)cg * 16u;
                uint32_t sw = swz128(off);
                *(uint4*)(smem + SM_AHI + sw) = make_uint4(hi4[0], hi4[1], hi4[2], hi4[3]);
                *(uint4*)(smem + SM_ALO + sw) = make_uint4(lo4[0], lo4[1], lo4[2], lo4[3]);
            }
        }
        TCGEN05_FENCE_BEFORE();
    }

    __syncthreads();
    if (wid == 0) TCGEN05_DEALLOC(tmem, 256);

    float* sP = (float*)(smem + SM_W);
    for (int idx = tid; idx < 4096; idx += 256) {
        int e = idx >> 6, h = idx & 63;
        sP[h * 65 + e] = w_l[(size_t)i * 4096 + idx];
    }
    __syncthreads();

    int bp = tid >> 1;
    int e0 = (tid & 1) * 32;
    float acc[32];
#pragma unroll
    for (int e = 0; e < 32; e++) acc[e] = b_l[i * 64 + e0 + e];
#pragma unroll 8
    for (int h = 0; h < 64; h++) {
        float hv = hbuf[bp * 65 + h];
#pragma unroll
        for (int e = 0; e < 32; e++) acc[e] = fmaf(sP[h * 65 + e0 + e], hv, acc[e]);
    }
    float* dst = d_feat + (size_t)(b0 + bp) * 448 + 64 + i * 64 + e0;
#pragma unroll
    for (int e = 0; e < 32; e++) dst[e] = tanhfast(acc[e]);
#endif  // HAS_TCGEN05
}

// ================= fp32 fallback LSTM =================
#define LSTM_SMEM_FLOATS (32768 + 2 * 8192 + 8192 + 256)
#define SXOFF 32768
#define SHOFF (32768 + 16384)
#define SBOFF (32768 + 16384 + 8192)

__device__ __forceinline__ void gemm_half(u64t acc[8][4], const float* __restrict__ vbase,
                                          const ulonglong2* __restrict__ sWp, int k0,
                                          int hc, int btb) {
#pragma unroll 4
    for (int kc = 0; kc < 32; kc++) {
        float2 vv[8];
#pragma unroll
        for (int bb = 0; bb < 8; bb++)
            vv[bb] = *(const float2*)(vbase + (btb + bb) * 64 + kc * 2);
#pragma unroll
        for (int kk = 0; kk < 2; kk++) {
            int k = k0 + kc * 2 + kk;
            ulonglong2 wlo = sWp[k * 64 + hc];
            ulonglong2 whi = sWp[k * 64 + 32 + hc];
#pragma unroll
            for (int bb = 0; bb < 8; bb++) {
                u64t vp = pk2(kk ? vv[bb].y : vv[bb].x);
                fma2(acc[bb][0], wlo.x, vp);
                fma2(acc[bb][1], wlo.y, vp);
                fma2(acc[bb][2], whi.x, vp);
                fma2(acc[bb][3], whi.y, vp);
            }
        }
    }
}

__global__ void __launch_bounds__(512, 1) lstm_fp32_kernel(const float* __restrict__ h0,
                                                           const float* __restrict__ c0,
                                                           const float* __restrict__ w_l,
                                                           const float* __restrict__ b_l) {
    if (d_useTC) return;
    extern __shared__ float sm[];
    float* sW = sm;
    float* sX = sm + SXOFF;
    float* sH = sm + SHOFF;
    float* sB = sm + SBOFF;
    int tid = threadIdx.x;
    int i = blockIdx.y;
    int b0 = blockIdx.x * 128;
    int hc = tid & 31;
    int btb = (tid >> 5) * 8;

    const float* wt = d_Wt + i * 32768;
#pragma unroll
    for (int j = 0; j < 16; j++) cpa16(sW + (tid + j * 512) * 4, wt + (tid + j * 512) * 4);
    {
        const float* mp = d_means + ((size_t)(5 * i + 0) * BATCH + b0) * 64;
        const float* hp = h0 + ((size_t)i * BATCH + b0) * 64;
#pragma unroll
        for (int j = 0; j < 4; j++) {
            int ch = tid + j * 512;
            cpa16(sX + ch * 4, mp + ch * 4);
            cpa16(sH + ch * 4, hp + ch * 4);
        }
    }
    asm volatile("cp.async.commit_group;");
    {
        const float* mp = d_means + ((size_t)(5 * i + 1) * BATCH + b0) * 64;
#pragma unroll
        for (int j = 0; j < 4; j++) {
            int ch = tid + j * 512;
            cpa16(sX + 8192 + ch * 4, mp + ch * 4);
        }
    }
    asm volatile("cp.async.commit_group;");

    if (tid < 256) sB[tid] = d_bias[i * 256 + tid];

    float cR[8][2];
#pragma unroll
    for (int bb = 0; bb < 8; bb++)
#pragma unroll
        for (int hp = 0; hp < 2; hp++)
            cR[bb][hp] = c0[((size_t)i * BATCH + b0 + btb + bb) * 64 + hc + hp * 32];

    const ulonglong2* sWp = (const ulonglong2*)sW;
    const ulonglong2* sBp = (const ulonglong2*)sB;

    for (int t = 0; t < 5; t++) {
        if (t < 4)
            asm volatile("cp.async.wait_group 1;");
        else
            asm volatile("cp.async.wait_group 0;");
        __syncthreads();

        u64t acc[8][4];
        {
            ulonglong2 bp0 = sBp[hc];
            ulonglong2 bp1 = sBp[32 + hc];
#pragma unroll
            for (int bb = 0; bb < 8; bb++) {
                acc[bb][0] = bp0.x;
                acc[bb][1] = bp0.y;
                acc[bb][2] = bp1.x;
                acc[bb][3] = bp1.y;
            }
        }
        gemm_half(acc, sX + (t & 1) * 8192, sWp, 0, hc, btb);
        gemm_half(acc, sH, sWp, 64, hc, btb);
        __syncthreads();

        if (t + 2 <= 4) {
            const float* mp = d_means + ((size_t)(5 * i + t + 2) * BATCH + b0) * 64;
#pragma unroll
            for (int j = 0; j < 4; j++) {
                int ch = tid + j * 512;
                cpa16(sX + (t & 1) * 8192 + ch * 4, mp + ch * 4);
            }
            asm volatile("cp.async.commit_group;");
        }

#pragma unroll
        for (int bb = 0; bb < 8; bb++) {
            int b = btb + bb;
#pragma unroll
            for (int hp = 0; hp < 2; hp++) {
                float gi, gf, gg, go;
                up2(acc[bb][hp * 2], gi, gf);
                up2(acc[bb][hp * 2 + 1], gg, go);
                float cc = sigf(gf) * cR[bb][hp] + sigf(gi) * tanhfast(gg);
                cR[bb][hp] = cc;
                sH[b * 64 + hc + hp * 32] = sigf(go) * tanhfast(cc);
            }
        }
    }
    __syncthreads();

    float* sP = sX;
    const float* wl = w_l + (size_t)i * 64 * 64;
    for (int idx = tid; idx < 4096; idx += 512) {
        int e = idx >> 6, h = idx & 63;
        sP[h * 65 + e] = wl[idx];
    }
    __syncthreads();

    float accp[8][2];
    {
        float bl0 = b_l[i * 64 + hc];
        float bl1 = b_l[i * 64 + 32 + hc];
#pragma unroll
        for (int bb = 0; bb < 8; bb++) {
            accp[bb][0] = bl0;
            accp[bb][1] = bl1;
        }
    }
#pragma unroll 8
    for (int h = 0; h < 64; h++) {
        float w0 = sP[h * 65 + hc];
        float w1 = sP[h * 65 + 32 + hc];
#pragma unroll
        for (int bb = 0; bb < 8; bb++) {
            float hv = sH[(btb + bb) * 64 + h];
            accp[bb][0] = fmaf(w0, hv, accp[bb][0]);
            accp[bb][1] = fmaf(w1, hv, accp[bb][1]);
        }
    }
#pragma unroll
    for (int bb = 0; bb < 8; bb++) {
        size_t base = (size_t)(b0 + btb + bb) * 448 + 64 + i * 64;
        d_feat[base + hc] = tanhfast(accp[bb][0]);
        d_feat[base + 32 + hc] = tanhfast(accp[bb][1]);
    }
}

// ---------------- final combine: split-barrier bulk weight stage ----------------
#define FINAL_SMEM_BYTES (169216 + 32)
#define FIN_MBAR0 169216
#define FIN_MBAR1 169224

__global__ void __launch_bounds__(256) final_kernel(
    const float* __restrict__ x, const float* __restrict__ dw_b,
    float* __restrict__ out) {
    extern __shared__ __align__(16) float sm[];
    float* swide2 = sm;                          // 81*64 floats @ 0
    float* scq2 = sm + 81 * 64;                  // @ 20736 B
    float* scqu2 = sm + 81 * 64 + 448 * 64;      // @ 135424 B
    float* sb2 = scqu2 + 128 * 64;               // @ 168192 B
    int tid = threadIdx.x;
    uint32_t sbase = smem_u32(sm);
    if (tid == 0) {
        MBARRIER_INIT(sbase + FIN_MBAR0, 1);
        MBARRIER_INIT(sbase + FIN_MBAR1, 1);
    }
    __syncthreads();
    if (tid == 0) {
        // barrier 0: wide weights + biases (small, needed first)
        MBARRIER_EXPECT_TX(sbase + FIN_MBAR0, 21760u);
        cpbulk(sbase + 0, d_wideT, 20736u, sbase + FIN_MBAR0);
        cpbulk(sbase + 168192, d_headB, 1024u, sbase + FIN_MBAR0);
        // barrier 1: cq + cqu (large, needed later)
        MBARRIER_EXPECT_TX(sbase + FIN_MBAR1, 147456u);
        cpbulk(sbase + 20736, d_cqT, 114688u, sbase + FIN_MBAR1);
        cpbulk(sbase + 135424, d_cquT, 32768u, sbase + FIN_MBAR1);
    }
    MBARRIER_WAIT_PARITY(sbase + FIN_MBAR0, 0);
    __syncthreads();

    const u64t* swide2u = (const u64t*)swide2;
    const u64t* scq2u = (const u64t*)scq2;
    const u64t* scqu2u = (const u64t*)scqu2;
    const u64t* sb2u = (const u64t*)sb2;

    int warp = tid >> 5, lane = tid & 31;
    float dwb0 = __ldg(dw_b);
    int bstart = blockIdx.x * 32 + warp * 4;

    // wide (overlaps with cq/cqu bulk copy in flight)
    u64t aw[4];
    {
        u64t bw = sb2u[lane];
#pragma unroll
        for (int t = 0; t < 4; t++) aw[t] = bw;
    }
#pragma unroll 3
    for (int j = 0; j < 81; j++) {
        float4 xv = __ldg((const float4*)(x + (size_t)j * BATCH + bstart));
        u64t w2 = swide2u[j * 32 + lane];
        fma2(aw[0], w2, pk2(xv.x));
        fma2(aw[1], w2, pk2(xv.y));
        fma2(aw[2], w2, pk2(xv.z));
        fma2(aw[3], w2, pk2(xv.w));
    }
    float w0[4], w1[4];
#pragma unroll
    for (int t = 0; t < 4; t++) {
        float a, b;
        up2(aw[t], a, b);
        w0[t] = tanhfast(a);
        w1[t] = tanhfast(b);
    }

    // wait for cq + cqu
    MBARRIER_WAIT_PARITY(sbase + FIN_MBAR1, 0);
    __syncthreads();

    u64t aq[4];
    {
        u64t bq = sb2u[32 + lane];
#pragma unroll
        for (int t = 0; t < 4; t++) aq[t] = bq;
    }
#pragma unroll 2
    for (int j4 = 0; j4 < 112; j4++) {
        float f0[4], f1[4], f2[4], f3[4];
        *(float4*)f0 = ((const float4*)(d_feat + (size_t)(bstart + 0) * 448))[j4];
        *(float4*)f1 = ((const float4*)(d_feat + (size_t)(bstart + 1) * 448))[j4];
        *(float4*)f2 = ((const float4*)(d_feat + (size_t)(bstart + 2) * 448))[j4];
        *(float4*)f3 = ((const float4*)(d_feat + (size_t)(bstart + 3) * 448))[j4];
#pragma unroll
        for (int jj = 0; jj < 4; jj++) {
            u64t w2 = scq2u[(j4 * 4 + jj) * 32 + lane];
            fma2(aq[0], w2, pk2(f0[jj]));
            fma2(aq[1], w2, pk2(f1[jj]));
            fma2(aq[2], w2, pk2(f2[jj]));
            fma2(aq[3], w2, pk2(f3[jj]));
        }
    }
    float q0[4], q1[4];
#pragma unroll
    for (int t = 0; t < 4; t++) {
        float a, b;
        up2(aq[t], a, b);
        q0[t] = tanhfast(a);
        q1[t] = tanhfast(b);
    }

#pragma unroll
    for (int t = 0; t < 4; t++) {
        u64t a = sb2u[64 + lane];
#pragma unroll
        for (int j = 0; j < 32; j++) {
            float v = __shfl_sync(0xffffffffu, q0[t], j);
            fma2(a, scqu2u[j * 32 + lane], pk2(v));
        }
#pragma unroll
        for (int j = 0; j < 32; j++) {
            float v = __shfl_sync(0xffffffffu, q1[t], j);
            fma2(a, scqu2u[(32 + j) * 32 + lane], pk2(v));
        }
#pragma unroll
        for (int j = 0; j < 32; j++) {
            float v = __shfl_sync(0xffffffffu, w0[t], j);
            fma2(a, scqu2u[(64 + j) * 32 + lane], pk2(v));
        }
#pragma unroll
        for (int j = 0; j < 32; j++) {
            float v = __shfl_sync(0xffffffffu, w1[t], j);
            fma2(a, scqu2u[(96 + j) * 32 + lane], pk2(v));
        }
        float x0, x1;
        up2(a, x0, x1);
        float qw0 = tanhfast(x0), qw1 = tanhfast(x1);
        float d0, d1;
        up2(sb2u[96 + lane], d0, d1);
        float r = d0 * qw0 + d1 * qw1;
#pragma unroll
        for (int off = 16; off; off >>= 1) r += __shfl_xor_sync(0xffffffffu, r, off);
        if (lane == 0) out[bstart + t] = r + dwb0;
    }
}

// ---------------- launch ----------------
extern "C" void kernel_launch(void* const* d_in, const int* in_sizes, int n_in,
                              void* d_out, int out_size) {
    const float* x = (const float*)d_in[0];
    const float* emb = (const float*)d_in[1];
    const float* Wih = (const float*)d_in[2];
    const float* Whh = (const float*)d_in[3];
    const float* bih = (const float*)d_in[4];
    const float* bhh = (const float*)d_in[5];
    const float* h0 = (const float*)d_in[6];
    const float* c0 = (const float*)d_in[7];
    const float* w_l = (const float*)d_in[8];
    const float* b_l = (const float*)d_in[9];
    const float* conv1_w = (const float*)d_in[10];
    const float* conv1_b = (const float*)d_in[11];
    const float* lin1_w = (const float*)d_in[12];
    const float* lin1_b = (const float*)d_in[13];
    const float* conv2_w = (const float*)d_in[14];
    const float* conv2_b = (const float*)d_in[15];
    const float* lin2_w = (const float*)d_in[16];
    const float* lin2_b = (const float*)d_in[17];
    const float* wide_w = (const float*)d_in[18];
    const float* wide_b = (const float*)d_in[19];
    const float* cq_w = (const float*)d_in[20];
    const float* cq_b = (const float*)d_in[21];
    const float* cqu_w = (const float*)d_in[22];
    const float* cqu_b = (const float*)d_in[23];
    const float* dw_w = (const float*)d_in[24];
    const float* dw_b = (const float*)d_in[25];
    float* out = (float*)d_out;

    prep_kernel<<<760, 256>>>(Wih, Whh, bih, bhh, wide_w, wide_b, cq_w, cq_b,
                              cqu_w, cqu_b, dw_w, x);
    mean_kernel<<<(31 * 2048) / 8, 256>>>(x, emb);

    cudaFuncSetAttribute(lstm_fp32_kernel, cudaFuncAttributeMaxDynamicSharedMemorySize,
                         LSTM_SMEM_FLOATS * 4);
    lstm_fp32_kernel<<<dim3(32, 4), 512, LSTM_SMEM_FLOATS * 4>>>(h0, c0, w_l, b_l);

    cudaFuncSetAttribute(lstm_tc_kernel, cudaFuncAttributeMaxDynamicSharedMemorySize,
                         TC_SMEM_BYTES);
    lstm_tc_kernel<<<148, 256, TC_SMEM_BYTES>>>(h0, c0, w_l, b_l,
                                                conv1_w, conv1_b, lin1_w, lin1_b,
                                                conv2_w, conv2_b, lin2_w, lin2_b);

    cudaFuncSetAttribute(final_kernel, cudaFuncAttributeMaxDynamicSharedMemorySize,
                         FINAL_SMEM_BYTES);
    final_kernel<<<128, 256, FINAL_SMEM_BYTES>>>(x, dw_b, out);
}